// round 1
// baseline (speedup 1.0000x reference)
#include <cuda_runtime.h>
#include <cstdint>

#define NMAX 20000
#define DF   512

// Scratch (static __device__ globals — no allocation in kernel_launch)
__device__ float g_bufA[(size_t)NMAX * DF];
__device__ float g_bufB[(size_t)NMAX * DF];
__device__ float g_bufC[(size_t)NMAX * DF];
__device__ float g_dinv[NMAX];

// ---------------------------------------------------------------------------
// Degree kernels: deg starts at 1 (self-loop), add real in-edges, then rsqrt.
// ---------------------------------------------------------------------------
__global__ void deg_init(float* deg, int n) {
    int i = blockIdx.x * blockDim.x + threadIdx.x;
    if (i < n) deg[i] = 1.0f;
}

__global__ void deg_count(float* deg, const int* __restrict__ dst, int E) {
    int e = blockIdx.x * blockDim.x + threadIdx.x;
    if (e < E) atomicAdd(&deg[dst[e]], 1.0f);
}

__global__ void deg_rsqrt(float* deg, int n) {
    int i = blockIdx.x * blockDim.x + threadIdx.x;
    if (i < n) deg[i] = rsqrtf(deg[i]);
}

// ---------------------------------------------------------------------------
// SGEMM 128x128x16, 256 threads, 8x8 per thread.
//  AMODE 0: A read raw
//  AMODE 1: A read = relu(a * dinv[row] + abias[kcol])   (fused GCN epilogue)
//  EMODE 0: C = acc
//  EMODE 1: v = acc * dinv[row]; C = v; C2 = v  (hs dual-store: gather src +
//           accumulator init == self-loop contribution)
//  EMODE 2: C = relu(acc + obias[col])
//  EMODE 3: C = acc + obias[col]
// ---------------------------------------------------------------------------
#define BM 128
#define BN 128
#define BK 16
#define TM 8
#define TN 8

template<int AMODE, int EMODE>
__global__ __launch_bounds__(256) void sgemm_kernel(
    const float* __restrict__ A, const float* __restrict__ B,
    float* __restrict__ C, float* __restrict__ C2,
    const float* __restrict__ abias, const float* __restrict__ obias,
    const float* __restrict__ dinv, int M, int N, int K)
{
    __shared__ float As[BK][BM + 4];
    __shared__ float Bs[BK][BN];

    const int tid = threadIdx.x;
    const int bm  = blockIdx.y * BM;
    const int bn  = blockIdx.x * BN;
    const int tx  = tid & 15;       // 0..15  -> col group
    const int ty  = tid >> 4;       // 0..15  -> row group

    // A tile load mapping: 128 rows x 16 cols; each thread loads 2 float4s
    const int arow = tid >> 2;          // 0..63 (and +64)
    const int acol = (tid & 3) * 4;     // 0,4,8,12
    // B tile load mapping: 16 rows x 128 cols; each thread loads 2 float4s
    const int brow = tid >> 5;          // 0..7 (and +8)
    const int bcol = (tid & 31) * 4;    // 0..124

    float acc[TM][TN];
    #pragma unroll
    for (int i = 0; i < TM; i++)
        #pragma unroll
        for (int j = 0; j < TN; j++) acc[i][j] = 0.0f;

    for (int k0 = 0; k0 < K; k0 += BK) {
        // ---- load A tile (with optional fused relu(a*dinv+bias)) ----
        #pragma unroll
        for (int h = 0; h < 2; h++) {
            int r = arow + h * 64;
            int grow = bm + r;
            float4 av = make_float4(0.f, 0.f, 0.f, 0.f);
            if (grow < M) {
                av = *reinterpret_cast<const float4*>(&A[(size_t)grow * K + k0 + acol]);
                if (AMODE == 1) {
                    float dv = dinv[grow];
                    av.x = fmaxf(av.x * dv + abias[k0 + acol + 0], 0.f);
                    av.y = fmaxf(av.y * dv + abias[k0 + acol + 1], 0.f);
                    av.z = fmaxf(av.z * dv + abias[k0 + acol + 2], 0.f);
                    av.w = fmaxf(av.w * dv + abias[k0 + acol + 3], 0.f);
                }
            }
            As[acol + 0][r] = av.x;
            As[acol + 1][r] = av.y;
            As[acol + 2][r] = av.z;
            As[acol + 3][r] = av.w;
        }
        // ---- load B tile ----
        #pragma unroll
        for (int h = 0; h < 2; h++) {
            int r = brow + h * 8;
            float4 bv = *reinterpret_cast<const float4*>(&B[(size_t)(k0 + r) * N + bn + bcol]);
            *reinterpret_cast<float4*>(&Bs[r][bcol]) = bv;
        }
        __syncthreads();

        #pragma unroll
        for (int kk = 0; kk < BK; kk++) {
            float a[TM], b[TN];
            #pragma unroll
            for (int i = 0; i < TM; i++) a[i] = As[kk][ty * TM + i];
            #pragma unroll
            for (int j = 0; j < TN; j++) b[j] = Bs[kk][tx * TN + j];
            #pragma unroll
            for (int i = 0; i < TM; i++)
                #pragma unroll
                for (int j = 0; j < TN; j++)
                    acc[i][j] += a[i] * b[j];
        }
        __syncthreads();
    }

    // ---- epilogue ----
    #pragma unroll
    for (int i = 0; i < TM; i++) {
        int row = bm + ty * TM + i;
        if (row >= M) continue;
        float dv = (EMODE == 1) ? dinv[row] : 0.0f;
        #pragma unroll
        for (int j = 0; j < TN; j += 4) {
            int col = bn + tx * TN + j;
            float4 v;
            if (EMODE == 0) {
                v = make_float4(acc[i][j], acc[i][j+1], acc[i][j+2], acc[i][j+3]);
            } else if (EMODE == 1) {
                v = make_float4(acc[i][j] * dv, acc[i][j+1] * dv,
                                acc[i][j+2] * dv, acc[i][j+3] * dv);
            } else if (EMODE == 2) {
                v = make_float4(fmaxf(acc[i][j]   + obias[col+0], 0.f),
                                fmaxf(acc[i][j+1] + obias[col+1], 0.f),
                                fmaxf(acc[i][j+2] + obias[col+2], 0.f),
                                fmaxf(acc[i][j+3] + obias[col+3], 0.f));
            } else {  // EMODE 3
                v = make_float4(acc[i][j]   + obias[col+0],
                                acc[i][j+1] + obias[col+1],
                                acc[i][j+2] + obias[col+2],
                                acc[i][j+3] + obias[col+3]);
            }
            *reinterpret_cast<float4*>(&C[(size_t)row * N + col]) = v;
            if (EMODE == 1)
                *reinterpret_cast<float4*>(&C2[(size_t)row * N + col]) = v;
        }
    }
}

// ---------------------------------------------------------------------------
// Edge scatter: one warp per edge. acc[dst] += hs[src]  (512 floats/edge)
// Uses vector reductions red.global.add.v4.f32 (sm_90+) — 32 red ops/edge.
// ---------------------------------------------------------------------------
__global__ __launch_bounds__(256) void scatter_add(
    const float* __restrict__ srcBuf, float* __restrict__ dstBuf,
    const int* __restrict__ srcIdx, const int* __restrict__ dstIdx, int E)
{
    int w    = (blockIdx.x * blockDim.x + threadIdx.x) >> 5;
    int lane = threadIdx.x & 31;
    if (w >= E) return;
    int s = srcIdx[w];
    int d = dstIdx[w];
    const float4* sp = reinterpret_cast<const float4*>(srcBuf + (size_t)s * DF);
    float4*       dp = reinterpret_cast<float4*>(dstBuf + (size_t)d * DF);
    #pragma unroll
    for (int i = 0; i < 4; i++) {
        float4 v = sp[lane + i * 32];
        asm volatile("red.global.add.v4.f32 [%0], {%1, %2, %3, %4};"
                     :: "l"(dp + lane + i * 32),
                        "f"(v.x), "f"(v.y), "f"(v.z), "f"(v.w)
                     : "memory");
    }
}

// ---------------------------------------------------------------------------
// Row softmax over 128 cols: one warp per row, 4 elems per lane.
// ---------------------------------------------------------------------------
__global__ __launch_bounds__(256) void softmax128(
    const float* __restrict__ in, float* __restrict__ out, int n)
{
    int row  = (blockIdx.x * blockDim.x + threadIdx.x) >> 5;
    int lane = threadIdx.x & 31;
    if (row >= n) return;
    float4 v = reinterpret_cast<const float4*>(in + (size_t)row * 128)[lane];
    float m = fmaxf(fmaxf(v.x, v.y), fmaxf(v.z, v.w));
    #pragma unroll
    for (int o = 16; o > 0; o >>= 1) m = fmaxf(m, __shfl_xor_sync(0xFFFFFFFFu, m, o));
    float e0 = expf(v.x - m), e1 = expf(v.y - m), e2 = expf(v.z - m), e3 = expf(v.w - m);
    float s = e0 + e1 + e2 + e3;
    #pragma unroll
    for (int o = 16; o > 0; o >>= 1) s += __shfl_xor_sync(0xFFFFFFFFu, s, o);
    float inv = 1.0f / s;
    reinterpret_cast<float4*>(out + (size_t)row * 128)[lane] =
        make_float4(e0 * inv, e1 * inv, e2 * inv, e3 * inv);
}

// ---------------------------------------------------------------------------
// kernel_launch
// Inputs (metadata order): x, edge_index, W1, b1, W2, b2, Wf1, bf1, Wf2, bf2
// ---------------------------------------------------------------------------
extern "C" void kernel_launch(void* const* d_in, const int* in_sizes, int n_in,
                              void* d_out, int out_size)
{
    const float* x   = (const float*)d_in[0];
    const int*   ei  = (const int*)  d_in[1];
    const float* W1  = (const float*)d_in[2];
    const float* b1  = (const float*)d_in[3];
    const float* W2  = (const float*)d_in[4];
    const float* b2  = (const float*)d_in[5];
    const float* Wf1 = (const float*)d_in[6];
    const float* bf1 = (const float*)d_in[7];
    const float* Wf2 = (const float*)d_in[8];
    const float* bf2 = (const float*)d_in[9];

    const int N = in_sizes[0] / DF;   // 20000
    const int E = in_sizes[1] / 2;    // 320000
    const int* srcIdx = ei;
    const int* dstIdx = ei + E;

    float *bufA, *bufB, *bufC, *dinv;
    cudaGetSymbolAddress((void**)&bufA, g_bufA);
    cudaGetSymbolAddress((void**)&bufB, g_bufB);
    cudaGetSymbolAddress((void**)&bufC, g_bufC);
    cudaGetSymbolAddress((void**)&dinv, g_dinv);

    const int nb  = (N + 255) / 256;
    const int eb  = (E + 255) / 256;
    const int swb = (E * 32 + 255) / 256;   // scatter: one warp per edge
    const int smb = (N * 32 + 255) / 256;   // softmax: one warp per row

    // degrees -> dinv
    deg_init <<<nb, 256>>>(dinv, N);
    deg_count<<<eb, 256>>>(dinv, dstIdx, E);
    deg_rsqrt<<<nb, 256>>>(dinv, N);

    dim3 blk(256);
    dim3 g512(512 / BN, (N + BM - 1) / BM);
    dim3 g128(128 / BN, (N + BM - 1) / BM);

    // Layer 1: hs1 = (x@W1)*dinv  -> bufA (gather src), bufB (accum init = self-loop)
    sgemm_kernel<0, 1><<<g512, blk>>>(x, W1, bufA, bufB, nullptr, nullptr, dinv, N, DF, DF);
    scatter_add<<<swb, 256>>>(bufA, bufB, srcIdx, dstIdx, E);

    // Layer 2: A-read = relu(bufB*dinv + b1); hs2 -> bufA (gather), bufC (accum)
    sgemm_kernel<1, 1><<<g512, blk>>>(bufB, W2, bufA, bufC, b1, nullptr, dinv, N, DF, DF);
    scatter_add<<<swb, 256>>>(bufA, bufC, srcIdx, dstIdx, E);

    // FC1: A-read = relu(bufC*dinv + b2); h3 = relu(.@Wf1 + bf1) -> bufB
    sgemm_kernel<1, 2><<<g512, blk>>>(bufC, Wf1, bufB, nullptr, b2, bf1, dinv, N, DF, DF);

    // FC2: logits = h3@Wf2 + bf2 -> bufA (first 20000x128 of it)
    sgemm_kernel<0, 3><<<g128, blk>>>(bufB, Wf2, bufA, nullptr, nullptr, bf2, nullptr, N, 128, DF);

    // softmax -> d_out
    softmax128<<<smb, 256>>>(bufA, (float*)d_out, N);
}

// round 3
// speedup vs baseline: 1.4741x; 1.4741x over previous
#include <cuda_runtime.h>
#include <cuda_bf16.h>
#include <cstdint>

#define NMAX 20000
#define DF   512

// ---------------- scratch (static device globals; no allocs) ----------------
__device__ float g_bufA[(size_t)NMAX * DF];   // fp32 gather source / logits
__device__ float g_bufB[(size_t)NMAX * DF];   // fp32 scatter accumulator
__device__ __nv_bfloat16 g_ah[(size_t)NMAX * DF];  // activation hi
__device__ __nv_bfloat16 g_al[(size_t)NMAX * DF];  // activation lo
__device__ __nv_bfloat16 g_bh[(size_t)NMAX * DF];  // fc1-out hi
__device__ __nv_bfloat16 g_bl[(size_t)NMAX * DF];  // fc1-out lo
__device__ __nv_bfloat16 g_wh[3 * 512 * 512 + 128 * 512]; // weights hi (transposed [N][K])
__device__ __nv_bfloat16 g_wl[3 * 512 * 512 + 128 * 512]; // weights lo
__device__ float g_dinv[NMAX];

// ---------------------------------------------------------------------------
// helpers
// ---------------------------------------------------------------------------
__device__ __forceinline__ void split_pair(float x, float y, uint32_t& hi, uint32_t& lo) {
    __nv_bfloat162 h = __floats2bfloat162_rn(x, y);
    float rx = x - __bfloat162float(h.x);
    float ry = y - __bfloat162float(h.y);
    __nv_bfloat162 l = __floats2bfloat162_rn(rx, ry);
    hi = *reinterpret_cast<uint32_t*>(&h);
    lo = *reinterpret_cast<uint32_t*>(&l);
}

#define CP_ASYNC16(dst, src) \
    asm volatile("cp.async.cg.shared.global [%0], [%1], 16;" :: "r"(dst), "l"(src))
#define CP_COMMIT() asm volatile("cp.async.commit_group;")
#define CP_WAIT0()  asm volatile("cp.async.wait_group 0;")
#define CP_WAIT1()  asm volatile("cp.async.wait_group 1;")

#define LDSM4(R, addr) \
    asm volatile("ldmatrix.sync.aligned.m8n8.x4.shared.b16 {%0,%1,%2,%3}, [%4];" \
                 : "=r"((R)[0]), "=r"((R)[1]), "=r"((R)[2]), "=r"((R)[3]) : "r"(addr))

#define MMA16816(d, a, b) \
    asm volatile("mma.sync.aligned.m16n8k16.row.col.f32.bf16.bf16.f32 " \
                 "{%0,%1,%2,%3}, {%4,%5,%6,%7}, {%8,%9}, {%0,%1,%2,%3};" \
                 : "+f"((d)[0]), "+f"((d)[1]), "+f"((d)[2]), "+f"((d)[3]) \
                 : "r"((a)[0]), "r"((a)[1]), "r"((a)[2]), "r"((a)[3]), \
                   "r"((b)[0]), "r"((b)[1]))

// ---------------------------------------------------------------------------
// degree kernels
// ---------------------------------------------------------------------------
__global__ void deg_init(float* deg, int n) {
    int i = blockIdx.x * blockDim.x + threadIdx.x;
    if (i < n) deg[i] = 1.0f;
}
__global__ void deg_count(float* deg, const int* __restrict__ dst, int E) {
    int e = blockIdx.x * blockDim.x + threadIdx.x;
    if (e < E) atomicAdd(&deg[dst[e]], 1.0f);
}
__global__ void deg_rsqrt(float* deg, int n) {
    int i = blockIdx.x * blockDim.x + threadIdx.x;
    if (i < n) deg[i] = rsqrtf(deg[i]);
}

// ---------------------------------------------------------------------------
// weight convert: W [K][N] fp32 -> transposed hi/lo bf16 [N][K]
// ---------------------------------------------------------------------------
__global__ void wconv_kernel(const float* __restrict__ W,
                             __nv_bfloat16* __restrict__ oh,
                             __nv_bfloat16* __restrict__ ol, int K, int N) {
    int idx = blockIdx.x * blockDim.x + threadIdx.x;   // idx = n*K + k (k fastest)
    if (idx >= K * N) return;
    int n = idx / K, k = idx % K;
    float w = W[(size_t)k * N + n];
    __nv_bfloat16 h = __float2bfloat16_rn(w);
    float r = w - __bfloat162float(h);
    oh[idx] = h;
    ol[idx] = __float2bfloat16_rn(r);
}

// ---------------------------------------------------------------------------
// activation split: optionally relu(v*dinv[row] + bias[col]) then hi/lo split
// ---------------------------------------------------------------------------
template<int T>
__global__ void split_kernel(const float* __restrict__ in,
                             __nv_bfloat16* __restrict__ oh,
                             __nv_bfloat16* __restrict__ ol,
                             const float* __restrict__ dinv,
                             const float* __restrict__ bias, int M) {
    int idx = blockIdx.x * blockDim.x + threadIdx.x;
    if (idx >= M * (DF / 4)) return;
    int row = idx >> 7;
    int c = (idx & 127) * 4;
    float4 v = *reinterpret_cast<const float4*>(&in[(size_t)row * DF + c]);
    if (T) {
        float dv = dinv[row];
        v.x = fmaxf(v.x * dv + bias[c + 0], 0.f);
        v.y = fmaxf(v.y * dv + bias[c + 1], 0.f);
        v.z = fmaxf(v.z * dv + bias[c + 2], 0.f);
        v.w = fmaxf(v.w * dv + bias[c + 3], 0.f);
    }
    uint32_t h0, l0, h1, l1;
    split_pair(v.x, v.y, h0, l0);
    split_pair(v.z, v.w, h1, l1);
    *reinterpret_cast<uint2*>(&oh[(size_t)row * DF + c]) = make_uint2(h0, h1);
    *reinterpret_cast<uint2*>(&ol[(size_t)row * DF + c]) = make_uint2(l0, l1);
}

// ---------------------------------------------------------------------------
// bf16x3 tensor-core GEMM. C[M,N] = A[M,512] @ B[N,512]^T  (B row = out col)
// BM=BN=128, BK=16, 256 threads (8 warps as 2x4), warp tile 64x32.
// Smem rows padded 16->24 bf16 (48B) for conflict-free ldmatrix.
//  EMODE 1: v = acc*dinv[row]; C=v; C2=v   (GCN hs dual-store)
//  EMODE 2: r = relu(acc+obias[col]); Oh/Ol = bf16 split(r)
//  EMODE 3: C = acc + obias[col]
// ---------------------------------------------------------------------------
#define SROW 48            // padded row bytes (24 bf16)
#define STAGE_BYTES 24576  // 4 tiles * 128 * 48
#define OFF_AL 6144
#define OFF_BH 12288
#define OFF_BL 18432

template<int EMODE>
__global__ __launch_bounds__(256, 1) void gemm_bf16x3(
    const __nv_bfloat16* __restrict__ Ah, const __nv_bfloat16* __restrict__ Al,
    const __nv_bfloat16* __restrict__ Bh, const __nv_bfloat16* __restrict__ Bl,
    float* __restrict__ C, float* __restrict__ C2,
    __nv_bfloat16* __restrict__ Oh, __nv_bfloat16* __restrict__ Ol,
    const float* __restrict__ obias, const float* __restrict__ dinv,
    int M, int N)
{
    __shared__ __align__(16) char smem[2 * STAGE_BYTES];

    const int tid  = threadIdx.x;
    const int lane = tid & 31;
    const int wid  = tid >> 5;
    const int wm   = wid >> 2;   // 0..1
    const int wn   = wid & 3;    // 0..3
    const int bm   = blockIdx.y * 128;
    const int bn   = blockIdx.x * 128;

    const uint32_t sb = (uint32_t)__cvta_generic_to_shared(smem);

    // loader coords: thread -> (row 0..127, 16B chunk 0..1)
    const int lrow = tid >> 1;
    const int lcb  = (tid & 1) * 16;      // smem byte chunk
    const int lce  = (tid & 1) * 8;       // global bf16 element offset

    const int arow = min(bm + lrow, M - 1);
    const int brow = bn + lrow;
    const __nv_bfloat16* gAh = Ah + (size_t)arow * DF + lce;
    const __nv_bfloat16* gAl = Al + (size_t)arow * DF + lce;
    const __nv_bfloat16* gBh = Bh + (size_t)brow * DF + lce;
    const __nv_bfloat16* gBl = Bl + (size_t)brow * DF + lce;
    const uint32_t sdst = sb + lrow * SROW + lcb;

    float acc[4][4][4];
    #pragma unroll
    for (int i = 0; i < 4; i++)
        #pragma unroll
        for (int j = 0; j < 4; j++)
            #pragma unroll
            for (int k = 0; k < 4; k++) acc[i][j][k] = 0.f;

    // prologue: stage 0
    {
        CP_ASYNC16(sdst,           gAh);
        CP_ASYNC16(sdst + OFF_AL,  gAl);
        CP_ASYNC16(sdst + OFF_BH,  gBh);
        CP_ASYNC16(sdst + OFF_BL,  gBl);
        CP_COMMIT();
    }

    // ldmatrix lane coords
    const int ar  = (lane & 7) + ((lane >> 3) & 1) * 8;
    const int akc = ((lane >> 4) & 1) * 8;
    const int br  = (lane & 7) + ((lane >> 4) & 1) * 8;
    const int bkc = ((lane >> 3) & 1) * 8;

    const int NSTAGE = DF / 16;  // 32
    for (int s = 0; s < NSTAGE; s++) {
        if (s + 1 < NSTAGE) {
            int koff = (s + 1) * 16;
            uint32_t d = sdst + ((s + 1) & 1) * STAGE_BYTES;
            CP_ASYNC16(d,          gAh + koff);
            CP_ASYNC16(d + OFF_AL, gAl + koff);
            CP_ASYNC16(d + OFF_BH, gBh + koff);
            CP_ASYNC16(d + OFF_BL, gBl + koff);
            CP_COMMIT();
            CP_WAIT1();
        } else {
            CP_WAIT0();
        }
        __syncthreads();

        const uint32_t s0 = sb + (s & 1) * STAGE_BYTES;

        uint32_t ahf[4][4], alf[4][4], bhf[4][2], blf[4][2];
        #pragma unroll
        for (int mt = 0; mt < 4; mt++) {
            uint32_t ad = s0 + (wm * 64 + mt * 16 + ar) * SROW + akc * 2;
            LDSM4(ahf[mt], ad);
            LDSM4(alf[mt], ad + OFF_AL);
        }
        #pragma unroll
        for (int h = 0; h < 2; h++) {
            uint32_t bd = s0 + OFF_BH + (wn * 32 + h * 16 + br) * SROW + bkc * 2;
            uint32_t r[4];
            LDSM4(r, bd);
            bhf[h * 2][0] = r[0]; bhf[h * 2][1] = r[1];
            bhf[h * 2 + 1][0] = r[2]; bhf[h * 2 + 1][1] = r[3];
            LDSM4(r, bd + OFF_AL);   // BL sits at BH + 6144
            blf[h * 2][0] = r[0]; blf[h * 2][1] = r[1];
            blf[h * 2 + 1][0] = r[2]; blf[h * 2 + 1][1] = r[3];
        }

        #pragma unroll
        for (int mt = 0; mt < 4; mt++)
            #pragma unroll
            for (int nt = 0; nt < 4; nt++) {
                MMA16816(acc[mt][nt], ahf[mt], bhf[nt]);
                MMA16816(acc[mt][nt], alf[mt], bhf[nt]);
                MMA16816(acc[mt][nt], ahf[mt], blf[nt]);
            }
        __syncthreads();
    }

    // epilogue
    #pragma unroll
    for (int mt = 0; mt < 4; mt++) {
        int rbase = bm + wm * 64 + mt * 16 + (lane >> 2);
        #pragma unroll
        for (int half = 0; half < 2; half++) {
            int r = rbase + half * 8;
            if (r >= M) continue;
            float dv = (EMODE == 1) ? dinv[r] : 0.f;
            #pragma unroll
            for (int nt = 0; nt < 4; nt++) {
                int c = bn + wn * 32 + nt * 8 + (lane & 3) * 2;
                float x = acc[mt][nt][half * 2];
                float y = acc[mt][nt][half * 2 + 1];
                if (EMODE == 1) {
                    x *= dv; y *= dv;
                    *reinterpret_cast<float2*>(&C [(size_t)r * N + c]) = make_float2(x, y);
                    *reinterpret_cast<float2*>(&C2[(size_t)r * N + c]) = make_float2(x, y);
                } else if (EMODE == 2) {
                    x = fmaxf(x + obias[c], 0.f);
                    y = fmaxf(y + obias[c + 1], 0.f);
                    uint32_t hi, lo;
                    split_pair(x, y, hi, lo);
                    *reinterpret_cast<uint32_t*>(&Oh[(size_t)r * DF + c]) = hi;
                    *reinterpret_cast<uint32_t*>(&Ol[(size_t)r * DF + c]) = lo;
                } else {  // EMODE 3
                    x += obias[c];
                    y += obias[c + 1];
                    *reinterpret_cast<float2*>(&C[(size_t)r * N + c]) = make_float2(x, y);
                }
            }
        }
    }
}

// ---------------------------------------------------------------------------
// edge scatter: one warp per edge; vector global reductions
// ---------------------------------------------------------------------------
__global__ __launch_bounds__(256) void scatter_add(
    const float* __restrict__ srcBuf, float* __restrict__ dstBuf,
    const int* __restrict__ srcIdx, const int* __restrict__ dstIdx, int E)
{
    int w    = (blockIdx.x * blockDim.x + threadIdx.x) >> 5;
    int lane = threadIdx.x & 31;
    if (w >= E) return;
    int s = srcIdx[w];
    int d = dstIdx[w];
    const float4* sp = reinterpret_cast<const float4*>(srcBuf + (size_t)s * DF);
    float4*       dp = reinterpret_cast<float4*>(dstBuf + (size_t)d * DF);
    #pragma unroll
    for (int i = 0; i < 4; i++) {
        float4 v = sp[lane + i * 32];
        asm volatile("red.global.add.v4.f32 [%0], {%1, %2, %3, %4};"
                     :: "l"(dp + lane + i * 32),
                        "f"(v.x), "f"(v.y), "f"(v.z), "f"(v.w)
                     : "memory");
    }
}

// ---------------------------------------------------------------------------
// row softmax over 128 cols: one warp per row
// ---------------------------------------------------------------------------
__global__ __launch_bounds__(256) void softmax128(
    const float* __restrict__ in, float* __restrict__ out, int n)
{
    int row  = (blockIdx.x * blockDim.x + threadIdx.x) >> 5;
    int lane = threadIdx.x & 31;
    if (row >= n) return;
    float4 v = reinterpret_cast<const float4*>(in + (size_t)row * 128)[lane];
    float m = fmaxf(fmaxf(v.x, v.y), fmaxf(v.z, v.w));
    #pragma unroll
    for (int o = 16; o > 0; o >>= 1) m = fmaxf(m, __shfl_xor_sync(0xFFFFFFFFu, m, o));
    float e0 = expf(v.x - m), e1 = expf(v.y - m), e2 = expf(v.z - m), e3 = expf(v.w - m);
    float s = e0 + e1 + e2 + e3;
    #pragma unroll
    for (int o = 16; o > 0; o >>= 1) s += __shfl_xor_sync(0xFFFFFFFFu, s, o);
    float inv = 1.0f / s;
    reinterpret_cast<float4*>(out + (size_t)row * 128)[lane] =
        make_float4(e0 * inv, e1 * inv, e2 * inv, e3 * inv);
}

// ---------------------------------------------------------------------------
// kernel_launch — inputs: x, edge_index, W1, b1, W2, b2, Wf1, bf1, Wf2, bf2
// ---------------------------------------------------------------------------
extern "C" void kernel_launch(void* const* d_in, const int* in_sizes, int n_in,
                              void* d_out, int out_size)
{
    const float* x   = (const float*)d_in[0];
    const int*   ei  = (const int*)  d_in[1];
    const float* W1  = (const float*)d_in[2];
    const float* b1  = (const float*)d_in[3];
    const float* W2  = (const float*)d_in[4];
    const float* b2  = (const float*)d_in[5];
    const float* Wf1 = (const float*)d_in[6];
    const float* bf1 = (const float*)d_in[7];
    const float* Wf2 = (const float*)d_in[8];
    const float* bf2 = (const float*)d_in[9];

    const int NV = in_sizes[0] / DF;   // 20000 nodes
    const int E  = in_sizes[1] / 2;    // 320000 edges
    const int* srcIdx = ei;
    const int* dstIdx = ei + E;

    float *bufA, *bufB, *dinv;
    __nv_bfloat16 *ah, *al, *bh, *bl, *wh, *wl;
    cudaGetSymbolAddress((void**)&bufA, g_bufA);
    cudaGetSymbolAddress((void**)&bufB, g_bufB);
    cudaGetSymbolAddress((void**)&dinv, g_dinv);
    cudaGetSymbolAddress((void**)&ah, g_ah);
    cudaGetSymbolAddress((void**)&al, g_al);
    cudaGetSymbolAddress((void**)&bh, g_bh);
    cudaGetSymbolAddress((void**)&bl, g_bl);
    cudaGetSymbolAddress((void**)&wh, g_wh);
    cudaGetSymbolAddress((void**)&wl, g_wl);

    const size_t W1o = 0, W2o = 512 * 512, Wf1o = 2 * 512 * 512, Wf2o = 3 * 512 * 512;

    const int nb  = (NV + 255) / 256;
    const int eb  = (E + 255) / 256;
    const int swb = (E * 32 + 255) / 256;
    const int smb = (NV * 32 + 255) / 256;
    const int spb = (NV * 128 + 255) / 256;

    // degrees
    deg_init <<<nb, 256>>>(dinv, NV);
    deg_count<<<eb, 256>>>(dinv, dstIdx, E);
    deg_rsqrt<<<nb, 256>>>(dinv, NV);

    // weight convert (transpose + hi/lo split)
    wconv_kernel<<<(512 * 512 + 255) / 256, 256>>>(W1,  wh + W1o,  wl + W1o,  512, 512);
    wconv_kernel<<<(512 * 512 + 255) / 256, 256>>>(W2,  wh + W2o,  wl + W2o,  512, 512);
    wconv_kernel<<<(512 * 512 + 255) / 256, 256>>>(Wf1, wh + Wf1o, wl + Wf1o, 512, 512);
    wconv_kernel<<<(512 * 128 + 255) / 256, 256>>>(Wf2, wh + Wf2o, wl + Wf2o, 512, 128);

    dim3 blk(256);
    dim3 g512(4, (NV + 127) / 128);
    dim3 g128(1, (NV + 127) / 128);

    // layer 1
    split_kernel<0><<<spb, 256>>>(x, ah, al, nullptr, nullptr, NV);
    gemm_bf16x3<1><<<g512, blk>>>(ah, al, wh + W1o, wl + W1o,
                                  bufA, bufB, nullptr, nullptr, nullptr, dinv, NV, 512);
    scatter_add<<<swb, 256>>>(bufA, bufB, srcIdx, dstIdx, E);

    // layer 2
    split_kernel<1><<<spb, 256>>>(bufB, ah, al, dinv, b1, NV);
    gemm_bf16x3<1><<<g512, blk>>>(ah, al, wh + W2o, wl + W2o,
                                  bufA, bufB, nullptr, nullptr, nullptr, dinv, NV, 512);
    scatter_add<<<swb, 256>>>(bufA, bufB, srcIdx, dstIdx, E);

    // fc1 (writes bf16 hi/lo directly)
    split_kernel<1><<<spb, 256>>>(bufB, ah, al, dinv, b2, NV);
    gemm_bf16x3<2><<<g512, blk>>>(ah, al, wh + Wf1o, wl + Wf1o,
                                  nullptr, nullptr, bh, bl, bf1, nullptr, NV, 512);

    // fc2 (logits)
    gemm_bf16x3<3><<<g128, blk>>>(bh, bl, wh + Wf2o, wl + Wf2o,
                                  bufA, nullptr, nullptr, nullptr, bf2, nullptr, NV, 128);

    // softmax
    softmax128<<<smb, 256>>>(bufA, (float*)d_out, NV);
}

// round 6
// speedup vs baseline: 1.7509x; 1.1878x over previous
#include <cuda_runtime.h>
#include <cuda_bf16.h>
#include <cstdint>

#define NMAX 20000
#define EMAX 400000
#define DF   512

// ---------------- scratch (static device globals; no allocs) ----------------
__device__ float g_bufA[(size_t)NMAX * DF];        // fp32 hs / logits
__device__ __nv_bfloat16 g_ah[(size_t)NMAX * DF];  // activation hi
__device__ __nv_bfloat16 g_al[(size_t)NMAX * DF];  // activation lo
__device__ __nv_bfloat16 g_bh[(size_t)NMAX * DF];  // fc1-out hi
__device__ __nv_bfloat16 g_bl[(size_t)NMAX * DF];  // fc1-out lo
__device__ __nv_bfloat16 g_wh[3 * 512 * 512 + 128 * 512]; // weights hi ([N][K])
__device__ __nv_bfloat16 g_wl[3 * 512 * 512 + 128 * 512]; // weights lo
__device__ float g_dinv[NMAX];
__device__ int   g_cnt[NMAX];
__device__ int   g_rowptr[NMAX + 1];
__device__ int   g_cursor[NMAX];
__device__ int   g_col[EMAX];
__device__ int   g_blocksum[256];

// ---------------------------------------------------------------------------
// helpers
// ---------------------------------------------------------------------------
__device__ __forceinline__ void split_pair(float x, float y, uint32_t& hi, uint32_t& lo) {
    __nv_bfloat162 h = __floats2bfloat162_rn(x, y);
    float rx = x - __bfloat162float(h.x);
    float ry = y - __bfloat162float(h.y);
    __nv_bfloat162 l = __floats2bfloat162_rn(rx, ry);
    hi = *reinterpret_cast<uint32_t*>(&h);
    lo = *reinterpret_cast<uint32_t*>(&l);
}

#define CP_ASYNC16(dst, src) \
    asm volatile("cp.async.cg.shared.global [%0], [%1], 16;" :: "r"(dst), "l"(src))
#define CP_COMMIT() asm volatile("cp.async.commit_group;")
#define CP_WAIT0()  asm volatile("cp.async.wait_group 0;")
#define CP_WAIT1()  asm volatile("cp.async.wait_group 1;")

#define LDSM4(R, addr) \
    asm volatile("ldmatrix.sync.aligned.m8n8.x4.shared.b16 {%0,%1,%2,%3}, [%4];" \
                 : "=r"((R)[0]), "=r"((R)[1]), "=r"((R)[2]), "=r"((R)[3]) : "r"(addr))

#define MMA16816(d, a, b) \
    asm volatile("mma.sync.aligned.m16n8k16.row.col.f32.bf16.bf16.f32 " \
                 "{%0,%1,%2,%3}, {%4,%5,%6,%7}, {%8,%9}, {%0,%1,%2,%3};" \
                 : "+f"((d)[0]), "+f"((d)[1]), "+f"((d)[2]), "+f"((d)[3]) \
                 : "r"((a)[0]), "r"((a)[1]), "r"((a)[2]), "r"((a)[3]), \
                   "r"((b)[0]), "r"((b)[1]))

// ---------------------------------------------------------------------------
// CSR build: histogram by dst -> scan (also emits dinv) -> fill col[]
// Scan restructured as one 256-thread block, 2-level (warp shuffle + smem).
// ---------------------------------------------------------------------------
__global__ void zero_cnt(int* cnt, int n) {
    int i = blockIdx.x * blockDim.x + threadIdx.x;
    if (i < n) cnt[i] = 0;
}
__global__ void hist_kernel(int* cnt, const int* __restrict__ dst, int E) {
    int e = blockIdx.x * blockDim.x + threadIdx.x;
    if (e < E) {
        int d = dst[e];
        if (d >= 0 && d < NMAX) atomicAdd(&cnt[d], 1);
    }
}
__global__ __launch_bounds__(256) void scan_kernel(
    const int* __restrict__ cnt, int* rowptr, int* cursor, float* dinv, int n)
{
    __shared__ int warpsum[8];
    const int tid  = threadIdx.x;
    const int lane = tid & 31;
    const int wrp  = tid >> 5;
    const int per  = (n + 255) / 256;            // 79 for n=20000
    const int begin = tid * per;
    const int stop  = min(begin + per, n);

    int local = 0;
    for (int i = begin; i < stop; i++) local += cnt[i];

    // inclusive scan of local across the block
    int v = local;
    #pragma unroll
    for (int o = 1; o < 32; o <<= 1) {
        int t = __shfl_up_sync(0xFFFFFFFFu, v, o);
        if (lane >= o) v += t;
    }
    if (lane == 31) warpsum[wrp] = v;
    __syncthreads();
    if (wrp == 0) {
        int w = (lane < 8) ? warpsum[lane] : 0;
        #pragma unroll
        for (int o = 1; o < 8; o <<= 1) {
            int t = __shfl_up_sync(0xFFFFFFFFu, w, o);
            if (lane >= o) w += t;
        }
        if (lane < 8) warpsum[lane] = w;
    }
    __syncthreads();
    int exclusive = v - local + ((wrp > 0) ? warpsum[wrp - 1] : 0);

    int run = exclusive;
    for (int i = begin; i < stop; i++) {
        rowptr[i] = run;
        cursor[i] = run;
        dinv[i]   = rsqrtf((float)cnt[i] + 1.0f);
        run += cnt[i];
    }
    if (tid == 255) rowptr[n] = warpsum[7];
}
__global__ void fill_kernel(const int* __restrict__ src, const int* __restrict__ dst,
                            int* cursor, int* col, int E) {
    int e = blockIdx.x * blockDim.x + threadIdx.x;
    if (e < E) {
        int d = dst[e];
        if (d >= 0 && d < NMAX) {
            int pos = atomicAdd(&cursor[d], 1);
            if (pos >= 0 && pos < EMAX) col[pos] = src[e];
        }
    }
}

// ---------------------------------------------------------------------------
// weight convert: W [K][N] fp32 -> transposed hi/lo bf16 [N][K]
// ---------------------------------------------------------------------------
__global__ void wconv_kernel(const float* __restrict__ W,
                             __nv_bfloat16* __restrict__ oh,
                             __nv_bfloat16* __restrict__ ol, int K, int N) {
    int idx = blockIdx.x * blockDim.x + threadIdx.x;
    if (idx >= K * N) return;
    int n = idx / K, k = idx % K;
    float w = W[(size_t)k * N + n];
    __nv_bfloat16 h = __float2bfloat16_rn(w);
    float r = w - __bfloat162float(h);
    oh[idx] = h;
    ol[idx] = __float2bfloat16_rn(r);
}

// ---------------------------------------------------------------------------
// plain split for input x (no transform)
// ---------------------------------------------------------------------------
__global__ void split0_kernel(const float* __restrict__ in,
                              __nv_bfloat16* __restrict__ oh,
                              __nv_bfloat16* __restrict__ ol, int M) {
    int idx = blockIdx.x * blockDim.x + threadIdx.x;
    if (idx >= M * (DF / 4)) return;
    int row = idx >> 7;
    int c = (idx & 127) * 4;
    float4 v = *reinterpret_cast<const float4*>(&in[(size_t)row * DF + c]);
    uint32_t h0, l0, h1, l1;
    split_pair(v.x, v.y, h0, l0);
    split_pair(v.z, v.w, h1, l1);
    *reinterpret_cast<uint2*>(&oh[(size_t)row * DF + c]) = make_uint2(h0, h1);
    *reinterpret_cast<uint2*>(&ol[(size_t)row * DF + c]) = make_uint2(l0, l1);
}

// ---------------------------------------------------------------------------
// CSR gather + fused GCN epilogue: one warp per node, 128-thread blocks.
//   acc = hs[node] + sum hs[col[p]];  t = relu(acc*dinv[node] + bias)
//   (oh, ol) = bf16 hi/lo split of t
// ---------------------------------------------------------------------------
__global__ __launch_bounds__(128) void gather_csr(
    const float* __restrict__ hs, const int* __restrict__ rowptr,
    const int* __restrict__ col, const float* __restrict__ dinv,
    const float* __restrict__ bias,
    __nv_bfloat16* __restrict__ oh, __nv_bfloat16* __restrict__ ol, int n)
{
    int node = (blockIdx.x * blockDim.x + threadIdx.x) >> 5;
    int lane = threadIdx.x & 31;
    if (node >= n) return;

    const float4* self = reinterpret_cast<const float4*>(hs + (size_t)node * DF);
    float4 acc[4];
    #pragma unroll
    for (int i = 0; i < 4; i++) acc[i] = self[lane + 32 * i];

    int p = rowptr[node];
    int e = rowptr[node + 1];
    if (p < 0) p = 0;
    if (e > EMAX) e = EMAX;

    while (p + 2 <= e) {
        int c0 = col[p], c1 = col[p + 1];
        const float4* r0 = reinterpret_cast<const float4*>(hs + (size_t)c0 * DF);
        const float4* r1 = reinterpret_cast<const float4*>(hs + (size_t)c1 * DF);
        float4 a0[4], a1[4];
        #pragma unroll
        for (int i = 0; i < 4; i++) a0[i] = r0[lane + 32 * i];
        #pragma unroll
        for (int i = 0; i < 4; i++) a1[i] = r1[lane + 32 * i];
        #pragma unroll
        for (int i = 0; i < 4; i++) {
            acc[i].x += a0[i].x + a1[i].x;
            acc[i].y += a0[i].y + a1[i].y;
            acc[i].z += a0[i].z + a1[i].z;
            acc[i].w += a0[i].w + a1[i].w;
        }
        p += 2;
    }
    if (p < e) {
        const float4* r0 = reinterpret_cast<const float4*>(hs + (size_t)col[p] * DF);
        #pragma unroll
        for (int i = 0; i < 4; i++) {
            float4 a = r0[lane + 32 * i];
            acc[i].x += a.x; acc[i].y += a.y; acc[i].z += a.z; acc[i].w += a.w;
        }
    }

    const float dv = dinv[node];
    const float4* bias4 = reinterpret_cast<const float4*>(bias);
    #pragma unroll
    for (int i = 0; i < 4; i++) {
        int f = lane + 32 * i;
        int c = f * 4;
        float4 bv = bias4[f];
        float x0 = fmaxf(acc[i].x * dv + bv.x, 0.f);
        float x1 = fmaxf(acc[i].y * dv + bv.y, 0.f);
        float x2 = fmaxf(acc[i].z * dv + bv.z, 0.f);
        float x3 = fmaxf(acc[i].w * dv + bv.w, 0.f);
        uint32_t h0, l0, h1, l1;
        split_pair(x0, x1, h0, l0);
        split_pair(x2, x3, h1, l1);
        *reinterpret_cast<uint2*>(&oh[(size_t)node * DF + c]) = make_uint2(h0, h1);
        *reinterpret_cast<uint2*>(&ol[(size_t)node * DF + c]) = make_uint2(l0, l1);
    }
}

// ---------------------------------------------------------------------------
// bf16x3 tensor-core GEMM. C[M,N] = A[M,512] @ B[N,512]^T
//  EMODE 1: C = acc * dinv[row]
//  EMODE 2: r = relu(acc+obias); Oh/Ol = split(r)
//  EMODE 3: C = acc + obias
// ---------------------------------------------------------------------------
#define SROW 48
#define STAGE_BYTES 24576
#define OFF_AL 6144
#define OFF_BH 12288
#define OFF_BL 18432

template<int EMODE>
__global__ __launch_bounds__(256, 1) void gemm_bf16x3(
    const __nv_bfloat16* __restrict__ Ah, const __nv_bfloat16* __restrict__ Al,
    const __nv_bfloat16* __restrict__ Bh, const __nv_bfloat16* __restrict__ Bl,
    float* __restrict__ C,
    __nv_bfloat16* __restrict__ Oh, __nv_bfloat16* __restrict__ Ol,
    const float* __restrict__ obias, const float* __restrict__ dinv,
    int M, int N)
{
    __shared__ __align__(16) char smem[2 * STAGE_BYTES];

    const int tid  = threadIdx.x;
    const int lane = tid & 31;
    const int wid  = tid >> 5;
    const int wm   = wid >> 2;
    const int wn   = wid & 3;
    const int bm   = blockIdx.y * 128;
    const int bn   = blockIdx.x * 128;

    const uint32_t sb = (uint32_t)__cvta_generic_to_shared(smem);

    const int lrow = tid >> 1;
    const int lcb  = (tid & 1) * 16;
    const int lce  = (tid & 1) * 8;

    const int arow = min(bm + lrow, M - 1);
    const int brow = bn + lrow;
    const __nv_bfloat16* gAh = Ah + (size_t)arow * DF + lce;
    const __nv_bfloat16* gAl = Al + (size_t)arow * DF + lce;
    const __nv_bfloat16* gBh = Bh + (size_t)brow * DF + lce;
    const __nv_bfloat16* gBl = Bl + (size_t)brow * DF + lce;
    const uint32_t sdst = sb + lrow * SROW + lcb;

    float acc[4][4][4];
    #pragma unroll
    for (int i = 0; i < 4; i++)
        #pragma unroll
        for (int j = 0; j < 4; j++)
            #pragma unroll
            for (int k = 0; k < 4; k++) acc[i][j][k] = 0.f;

    {
        CP_ASYNC16(sdst,           gAh);
        CP_ASYNC16(sdst + OFF_AL,  gAl);
        CP_ASYNC16(sdst + OFF_BH,  gBh);
        CP_ASYNC16(sdst + OFF_BL,  gBl);
        CP_COMMIT();
    }

    const int ar  = (lane & 7) + ((lane >> 3) & 1) * 8;
    const int akc = ((lane >> 4) & 1) * 8;
    const int br  = (lane & 7) + ((lane >> 4) & 1) * 8;
    const int bkc = ((lane >> 3) & 1) * 8;

    const int NSTAGE = DF / 16;
    for (int s = 0; s < NSTAGE; s++) {
        if (s + 1 < NSTAGE) {
            int koff = (s + 1) * 16;
            uint32_t d = sdst + ((s + 1) & 1) * STAGE_BYTES;
            CP_ASYNC16(d,          gAh + koff);
            CP_ASYNC16(d + OFF_AL, gAl + koff);
            CP_ASYNC16(d + OFF_BH, gBh + koff);
            CP_ASYNC16(d + OFF_BL, gBl + koff);
            CP_COMMIT();
            CP_WAIT1();
        } else {
            CP_WAIT0();
        }
        __syncthreads();

        const uint32_t s0 = sb + (s & 1) * STAGE_BYTES;

        uint32_t ahf[4][4], alf[4][4], bhf[4][2], blf[4][2];
        #pragma unroll
        for (int mt = 0; mt < 4; mt++) {
            uint32_t ad = s0 + (wm * 64 + mt * 16 + ar) * SROW + akc * 2;
            LDSM4(ahf[mt], ad);
            LDSM4(alf[mt], ad + OFF_AL);
        }
        #pragma unroll
        for (int h = 0; h < 2; h++) {
            uint32_t bd = s0 + OFF_BH + (wn * 32 + h * 16 + br) * SROW + bkc * 2;
            uint32_t r[4];
            LDSM4(r, bd);
            bhf[h * 2][0] = r[0]; bhf[h * 2][1] = r[1];
            bhf[h * 2 + 1][0] = r[2]; bhf[h * 2 + 1][1] = r[3];
            LDSM4(r, bd + OFF_AL);
            blf[h * 2][0] = r[0]; blf[h * 2][1] = r[1];
            blf[h * 2 + 1][0] = r[2]; blf[h * 2 + 1][1] = r[3];
        }

        #pragma unroll
        for (int mt = 0; mt < 4; mt++)
            #pragma unroll
            for (int nt = 0; nt < 4; nt++) {
                MMA16816(acc[mt][nt], ahf[mt], bhf[nt]);
                MMA16816(acc[mt][nt], alf[mt], bhf[nt]);
                MMA16816(acc[mt][nt], ahf[mt], blf[nt]);
            }
        __syncthreads();
    }

    #pragma unroll
    for (int mt = 0; mt < 4; mt++) {
        int rbase = bm + wm * 64 + mt * 16 + (lane >> 2);
        #pragma unroll
        for (int half = 0; half < 2; half++) {
            int r = rbase + half * 8;
            if (r >= M) continue;
            float dv = (EMODE == 1) ? dinv[r] : 0.f;
            #pragma unroll
            for (int nt = 0; nt < 4; nt++) {
                int c = bn + wn * 32 + nt * 8 + (lane & 3) * 2;
                float x = acc[mt][nt][half * 2];
                float y = acc[mt][nt][half * 2 + 1];
                if (EMODE == 1) {
                    x *= dv; y *= dv;
                    *reinterpret_cast<float2*>(&C[(size_t)r * N + c]) = make_float2(x, y);
                } else if (EMODE == 2) {
                    x = fmaxf(x + obias[c], 0.f);
                    y = fmaxf(y + obias[c + 1], 0.f);
                    uint32_t hi, lo;
                    split_pair(x, y, hi, lo);
                    *reinterpret_cast<uint32_t*>(&Oh[(size_t)r * DF + c]) = hi;
                    *reinterpret_cast<uint32_t*>(&Ol[(size_t)r * DF + c]) = lo;
                } else {
                    x += obias[c];
                    y += obias[c + 1];
                    *reinterpret_cast<float2*>(&C[(size_t)r * N + c]) = make_float2(x, y);
                }
            }
        }
    }
}

// ---------------------------------------------------------------------------
// row softmax over 128 cols: one warp per row
// ---------------------------------------------------------------------------
__global__ __launch_bounds__(256) void softmax128(
    const float* __restrict__ in, float* __restrict__ out, int n)
{
    int row  = (blockIdx.x * blockDim.x + threadIdx.x) >> 5;
    int lane = threadIdx.x & 31;
    if (row >= n) return;
    float4 v = reinterpret_cast<const float4*>(in + (size_t)row * 128)[lane];
    float m = fmaxf(fmaxf(v.x, v.y), fmaxf(v.z, v.w));
    #pragma unroll
    for (int o = 16; o > 0; o >>= 1) m = fmaxf(m, __shfl_xor_sync(0xFFFFFFFFu, m, o));
    float e0 = expf(v.x - m), e1 = expf(v.y - m), e2 = expf(v.z - m), e3 = expf(v.w - m);
    float s = e0 + e1 + e2 + e3;
    #pragma unroll
    for (int o = 16; o > 0; o >>= 1) s += __shfl_xor_sync(0xFFFFFFFFu, s, o);
    float inv = 1.0f / s;
    reinterpret_cast<float4*>(out + (size_t)row * 128)[lane] =
        make_float4(e0 * inv, e1 * inv, e2 * inv, e3 * inv);
}

// ---------------------------------------------------------------------------
// kernel_launch — inputs: x, edge_index, W1, b1, W2, b2, Wf1, bf1, Wf2, bf2
// ---------------------------------------------------------------------------
extern "C" void kernel_launch(void* const* d_in, const int* in_sizes, int n_in,
                              void* d_out, int out_size)
{
    const float* x   = (const float*)d_in[0];
    const int*   ei  = (const int*)  d_in[1];
    const float* W1  = (const float*)d_in[2];
    const float* b1  = (const float*)d_in[3];
    const float* W2  = (const float*)d_in[4];
    const float* b2  = (const float*)d_in[5];
    const float* Wf1 = (const float*)d_in[6];
    const float* bf1 = (const float*)d_in[7];
    const float* Wf2 = (const float*)d_in[8];
    const float* bf2 = (const float*)d_in[9];

    const int NV = in_sizes[0] / DF;   // 20000
    const int E  = in_sizes[1] / 2;    // 320000
    const int* srcIdx = ei;
    const int* dstIdx = ei + E;

    float *bufA, *dinv;
    __nv_bfloat16 *ah, *al, *bh, *bl, *wh, *wl;
    int *cnt, *rowptr, *cursor, *col;
    cudaGetSymbolAddress((void**)&bufA, g_bufA);
    cudaGetSymbolAddress((void**)&dinv, g_dinv);
    cudaGetSymbolAddress((void**)&ah, g_ah);
    cudaGetSymbolAddress((void**)&al, g_al);
    cudaGetSymbolAddress((void**)&bh, g_bh);
    cudaGetSymbolAddress((void**)&bl, g_bl);
    cudaGetSymbolAddress((void**)&wh, g_wh);
    cudaGetSymbolAddress((void**)&wl, g_wl);
    cudaGetSymbolAddress((void**)&cnt, g_cnt);
    cudaGetSymbolAddress((void**)&rowptr, g_rowptr);
    cudaGetSymbolAddress((void**)&cursor, g_cursor);
    cudaGetSymbolAddress((void**)&col, g_col);

    const size_t W1o = 0, W2o = 512 * 512, Wf1o = 2 * 512 * 512, Wf2o = 3 * 512 * 512;

    const int nb  = (NV + 255) / 256;
    const int eb  = (E + 255) / 256;
    const int gwb = (NV * 32 + 127) / 128;   // gather: warp/node, 128-thr blocks
    const int smb = (NV * 32 + 255) / 256;
    const int spb = (NV * 128 + 255) / 256;

    // CSR build (also produces dinv)
    zero_cnt   <<<nb, 256>>>(cnt, NV);
    hist_kernel<<<eb, 256>>>(cnt, dstIdx, E);
    scan_kernel<<<1, 256>>>(cnt, rowptr, cursor, dinv, NV);
    fill_kernel<<<eb, 256>>>(srcIdx, dstIdx, cursor, col, E);

    // weight convert
    wconv_kernel<<<(512 * 512 + 255) / 256, 256>>>(W1,  wh + W1o,  wl + W1o,  512, 512);
    wconv_kernel<<<(512 * 512 + 255) / 256, 256>>>(W2,  wh + W2o,  wl + W2o,  512, 512);
    wconv_kernel<<<(512 * 512 + 255) / 256, 256>>>(Wf1, wh + Wf1o, wl + Wf1o, 512, 512);
    wconv_kernel<<<(512 * 128 + 255) / 256, 256>>>(Wf2, wh + Wf2o, wl + Wf2o, 512, 128);

    dim3 blk(256);
    dim3 g512(4, (NV + 127) / 128);
    dim3 g128(1, (NV + 127) / 128);

    // layer 1
    split0_kernel<<<spb, 256>>>(x, ah, al, NV);
    gemm_bf16x3<1><<<g512, blk>>>(ah, al, wh + W1o, wl + W1o,
                                  bufA, nullptr, nullptr, nullptr, dinv, NV, 512);
    gather_csr<<<gwb, 128>>>(bufA, rowptr, col, dinv, b1, ah, al, NV);

    // layer 2
    gemm_bf16x3<1><<<g512, blk>>>(ah, al, wh + W2o, wl + W2o,
                                  bufA, nullptr, nullptr, nullptr, dinv, NV, 512);
    gather_csr<<<gwb, 128>>>(bufA, rowptr, col, dinv, b2, ah, al, NV);

    // fc1
    gemm_bf16x3<2><<<g512, blk>>>(ah, al, wh + Wf1o, wl + Wf1o,
                                  nullptr, bh, bl, bf1, nullptr, NV, 512);

    // fc2
    gemm_bf16x3<3><<<g128, blk>>>(bh, bl, wh + Wf2o, wl + Wf2o,
                                  bufA, nullptr, nullptr, bf2, nullptr, NV, 128);

    // softmax -> d_out
    softmax128<<<smb, 256>>>(bufA, (float*)d_out, NV);
}

// round 7
// speedup vs baseline: 1.8713x; 1.0688x over previous
#include <cuda_runtime.h>
#include <cuda_bf16.h>
#include <cstdint>

#define NMAX 20000
#define EMAX 400000
#define DF   512

// ---------------- scratch (static device globals; no allocs) ----------------
__device__ float g_bufA[(size_t)NMAX * DF];        // fp32 hs / logits
__device__ __nv_bfloat16 g_ah[(size_t)NMAX * DF];  // activation hi
__device__ __nv_bfloat16 g_al[(size_t)NMAX * DF];  // activation lo
__device__ __nv_bfloat16 g_bh[(size_t)NMAX * DF];  // fc1-out hi
__device__ __nv_bfloat16 g_bl[(size_t)NMAX * DF];  // fc1-out lo
__device__ __nv_bfloat16 g_wh[3 * 512 * 512 + 128 * 512]; // weights hi ([N][K])
__device__ __nv_bfloat16 g_wl[3 * 512 * 512 + 128 * 512]; // weights lo
__device__ float g_dinv[NMAX];
__device__ int   g_cnt[NMAX];
__device__ int   g_rowptr[NMAX + 1];
__device__ int   g_cursor[NMAX];
__device__ int   g_col[EMAX];

// ---------------------------------------------------------------------------
// helpers
// ---------------------------------------------------------------------------
__device__ __forceinline__ void split_pair(float x, float y, uint32_t& hi, uint32_t& lo) {
    __nv_bfloat162 h = __floats2bfloat162_rn(x, y);
    float rx = x - __bfloat162float(h.x);
    float ry = y - __bfloat162float(h.y);
    __nv_bfloat162 l = __floats2bfloat162_rn(rx, ry);
    hi = *reinterpret_cast<uint32_t*>(&h);
    lo = *reinterpret_cast<uint32_t*>(&l);
}

#define CP_ASYNC16(dst, src) \
    asm volatile("cp.async.cg.shared.global [%0], [%1], 16;" :: "r"(dst), "l"(src))
#define CP_COMMIT() asm volatile("cp.async.commit_group;")
#define CP_WAIT0()  asm volatile("cp.async.wait_group 0;")
#define CP_WAIT1()  asm volatile("cp.async.wait_group 1;")

#define LDSM4(R, addr) \
    asm volatile("ldmatrix.sync.aligned.m8n8.x4.shared.b16 {%0,%1,%2,%3}, [%4];" \
                 : "=r"((R)[0]), "=r"((R)[1]), "=r"((R)[2]), "=r"((R)[3]) : "r"(addr))

#define MMA16816(d, a, b) \
    asm volatile("mma.sync.aligned.m16n8k16.row.col.f32.bf16.bf16.f32 " \
                 "{%0,%1,%2,%3}, {%4,%5,%6,%7}, {%8,%9}, {%0,%1,%2,%3};" \
                 : "+f"((d)[0]), "+f"((d)[1]), "+f"((d)[2]), "+f"((d)[3]) \
                 : "r"((a)[0]), "r"((a)[1]), "r"((a)[2]), "r"((a)[3]), \
                   "r"((b)[0]), "r"((b)[1]))

// ---------------------------------------------------------------------------
// CSR build (unchanged from R6-pass)
// ---------------------------------------------------------------------------
__global__ void zero_cnt(int* cnt, int n) {
    int i = blockIdx.x * blockDim.x + threadIdx.x;
    if (i < n) cnt[i] = 0;
}
__global__ void hist_kernel(int* cnt, const int* __restrict__ dst, int E) {
    int e = blockIdx.x * blockDim.x + threadIdx.x;
    if (e < E) {
        int d = dst[e];
        if (d >= 0 && d < NMAX) atomicAdd(&cnt[d], 1);
    }
}
__global__ __launch_bounds__(256) void scan_kernel(
    const int* __restrict__ cnt, int* rowptr, int* cursor, float* dinv, int n)
{
    __shared__ int warpsum[8];
    const int tid  = threadIdx.x;
    const int lane = tid & 31;
    const int wrp  = tid >> 5;
    const int per  = (n + 255) / 256;
    const int begin = tid * per;
    const int stop  = min(begin + per, n);

    int local = 0;
    for (int i = begin; i < stop; i++) local += cnt[i];

    int v = local;
    #pragma unroll
    for (int o = 1; o < 32; o <<= 1) {
        int t = __shfl_up_sync(0xFFFFFFFFu, v, o);
        if (lane >= o) v += t;
    }
    if (lane == 31) warpsum[wrp] = v;
    __syncthreads();
    if (wrp == 0) {
        int w = (lane < 8) ? warpsum[lane] : 0;
        #pragma unroll
        for (int o = 1; o < 8; o <<= 1) {
            int t = __shfl_up_sync(0xFFFFFFFFu, w, o);
            if (lane >= o) w += t;
        }
        if (lane < 8) warpsum[lane] = w;
    }
    __syncthreads();
    int exclusive = v - local + ((wrp > 0) ? warpsum[wrp - 1] : 0);

    int run = exclusive;
    for (int i = begin; i < stop; i++) {
        rowptr[i] = run;
        cursor[i] = run;
        dinv[i]   = rsqrtf((float)cnt[i] + 1.0f);
        run += cnt[i];
    }
    if (tid == 255) rowptr[n] = warpsum[7];
}
__global__ void fill_kernel(const int* __restrict__ src, const int* __restrict__ dst,
                            int* cursor, int* col, int E) {
    int e = blockIdx.x * blockDim.x + threadIdx.x;
    if (e < E) {
        int d = dst[e];
        if (d >= 0 && d < NMAX) {
            int pos = atomicAdd(&cursor[d], 1);
            if (pos >= 0 && pos < EMAX) col[pos] = src[e];
        }
    }
}

// ---------------------------------------------------------------------------
// weight convert: W [K][N] fp32 -> transposed hi/lo bf16 [N][K]
// ---------------------------------------------------------------------------
__global__ void wconv_kernel(const float* __restrict__ W,
                             __nv_bfloat16* __restrict__ oh,
                             __nv_bfloat16* __restrict__ ol, int K, int N) {
    int idx = blockIdx.x * blockDim.x + threadIdx.x;
    if (idx >= K * N) return;
    int n = idx / K, k = idx % K;
    float w = W[(size_t)k * N + n];
    __nv_bfloat16 h = __float2bfloat16_rn(w);
    float r = w - __bfloat162float(h);
    oh[idx] = h;
    ol[idx] = __float2bfloat16_rn(r);
}

// ---------------------------------------------------------------------------
// plain split for input x
// ---------------------------------------------------------------------------
__global__ void split0_kernel(const float* __restrict__ in,
                              __nv_bfloat16* __restrict__ oh,
                              __nv_bfloat16* __restrict__ ol, int M) {
    int idx = blockIdx.x * blockDim.x + threadIdx.x;
    if (idx >= M * (DF / 4)) return;
    int row = idx >> 7;
    int c = (idx & 127) * 4;
    float4 v = *reinterpret_cast<const float4*>(&in[(size_t)row * DF + c]);
    uint32_t h0, l0, h1, l1;
    split_pair(v.x, v.y, h0, l0);
    split_pair(v.z, v.w, h1, l1);
    *reinterpret_cast<uint2*>(&oh[(size_t)row * DF + c]) = make_uint2(h0, h1);
    *reinterpret_cast<uint2*>(&ol[(size_t)row * DF + c]) = make_uint2(l0, l1);
}

// ---------------------------------------------------------------------------
// CSR gather + fused GCN epilogue (unchanged from R6-pass)
// ---------------------------------------------------------------------------
__global__ __launch_bounds__(128) void gather_csr(
    const float* __restrict__ hs, const int* __restrict__ rowptr,
    const int* __restrict__ col, const float* __restrict__ dinv,
    const float* __restrict__ bias,
    __nv_bfloat16* __restrict__ oh, __nv_bfloat16* __restrict__ ol, int n)
{
    int node = (blockIdx.x * blockDim.x + threadIdx.x) >> 5;
    int lane = threadIdx.x & 31;
    if (node >= n) return;

    const float4* self = reinterpret_cast<const float4*>(hs + (size_t)node * DF);
    float4 acc[4];
    #pragma unroll
    for (int i = 0; i < 4; i++) acc[i] = self[lane + 32 * i];

    int p = rowptr[node];
    int e = rowptr[node + 1];
    if (p < 0) p = 0;
    if (e > EMAX) e = EMAX;

    while (p + 2 <= e) {
        int c0 = col[p], c1 = col[p + 1];
        const float4* r0 = reinterpret_cast<const float4*>(hs + (size_t)c0 * DF);
        const float4* r1 = reinterpret_cast<const float4*>(hs + (size_t)c1 * DF);
        float4 a0[4], a1[4];
        #pragma unroll
        for (int i = 0; i < 4; i++) a0[i] = r0[lane + 32 * i];
        #pragma unroll
        for (int i = 0; i < 4; i++) a1[i] = r1[lane + 32 * i];
        #pragma unroll
        for (int i = 0; i < 4; i++) {
            acc[i].x += a0[i].x + a1[i].x;
            acc[i].y += a0[i].y + a1[i].y;
            acc[i].z += a0[i].z + a1[i].z;
            acc[i].w += a0[i].w + a1[i].w;
        }
        p += 2;
    }
    if (p < e) {
        const float4* r0 = reinterpret_cast<const float4*>(hs + (size_t)col[p] * DF);
        #pragma unroll
        for (int i = 0; i < 4; i++) {
            float4 a = r0[lane + 32 * i];
            acc[i].x += a.x; acc[i].y += a.y; acc[i].z += a.z; acc[i].w += a.w;
        }
    }

    const float dv = dinv[node];
    const float4* bias4 = reinterpret_cast<const float4*>(bias);
    #pragma unroll
    for (int i = 0; i < 4; i++) {
        int f = lane + 32 * i;
        int c = f * 4;
        float4 bv = bias4[f];
        float x0 = fmaxf(acc[i].x * dv + bv.x, 0.f);
        float x1 = fmaxf(acc[i].y * dv + bv.y, 0.f);
        float x2 = fmaxf(acc[i].z * dv + bv.z, 0.f);
        float x3 = fmaxf(acc[i].w * dv + bv.w, 0.f);
        uint32_t h0, l0, h1, l1;
        split_pair(x0, x1, h0, l0);
        split_pair(x2, x3, h1, l1);
        *reinterpret_cast<uint2*>(&oh[(size_t)node * DF + c]) = make_uint2(h0, h1);
        *reinterpret_cast<uint2*>(&ol[(size_t)node * DF + c]) = make_uint2(l0, l1);
    }
}

// ---------------------------------------------------------------------------
// bf16x3 tensor-core GEMM — 3-stage cp.async pipeline, XOR-swizzled smem.
// Stage: 4 tiles (AH,AL,BH,BL) of 128 rows x 16 bf16 (32B rows, no pad).
// Swizzle: physical 16B-chunk = logical_chunk ^ ((row>>2)&1)  -> conflict-free
// ldmatrix and cp.async stores. 3 stages x 16KB = 48KB static smem exactly.
//  EMODE 1: C = acc * dinv[row]
//  EMODE 2: r = relu(acc+obias); Oh/Ol = split(r)
//  EMODE 3: C = acc + obias
// ---------------------------------------------------------------------------
#define SROW 32
#define TILE_BYTES 4096          // 128 * 32
#define STAGE_BYTES 16384        // 4 tiles
#define OFF_AL 4096
#define OFF_BH 8192
#define OFF_BL 12288

template<int EMODE>
__global__ __launch_bounds__(256, 1) void gemm_bf16x3(
    const __nv_bfloat16* __restrict__ Ah, const __nv_bfloat16* __restrict__ Al,
    const __nv_bfloat16* __restrict__ Bh, const __nv_bfloat16* __restrict__ Bl,
    float* __restrict__ C,
    __nv_bfloat16* __restrict__ Oh, __nv_bfloat16* __restrict__ Ol,
    const float* __restrict__ obias, const float* __restrict__ dinv,
    int M, int N)
{
    __shared__ __align__(16) char smem[3 * STAGE_BYTES];

    const int tid  = threadIdx.x;
    const int lane = tid & 31;
    const int wid  = tid >> 5;
    const int wm   = wid >> 2;
    const int wn   = wid & 3;
    const int bm   = blockIdx.y * 128;
    const int bn   = blockIdx.x * 128;

    const uint32_t sb = (uint32_t)__cvta_generic_to_shared(smem);

    // loader: thread -> (row 0..127, logical 16B chunk 0..1)
    const int lrow = tid >> 1;
    const int lchunk = tid & 1;
    const int pchunk = lchunk ^ ((lrow >> 2) & 1);      // swizzled
    const int lce  = lchunk * 8;                        // global bf16 offset

    const int arow = min(bm + lrow, M - 1);
    const int brow = bn + lrow;
    const __nv_bfloat16* gAh = Ah + (size_t)arow * DF + lce;
    const __nv_bfloat16* gAl = Al + (size_t)arow * DF + lce;
    const __nv_bfloat16* gBh = Bh + (size_t)brow * DF + lce;
    const __nv_bfloat16* gBl = Bl + (size_t)brow * DF + lce;
    const uint32_t sdst = sb + lrow * SROW + pchunk * 16;

    float acc[4][4][4];
    #pragma unroll
    for (int i = 0; i < 4; i++)
        #pragma unroll
        for (int j = 0; j < 4; j++)
            #pragma unroll
            for (int k = 0; k < 4; k++) acc[i][j][k] = 0.f;

    const int NSTAGE = DF / 16;   // 32

    // prologue: stages 0 and 1 in flight
    #pragma unroll
    for (int st = 0; st < 2; st++) {
        int koff = st * 16;
        uint32_t d = sdst + st * STAGE_BYTES;
        CP_ASYNC16(d,          gAh + koff);
        CP_ASYNC16(d + OFF_AL, gAl + koff);
        CP_ASYNC16(d + OFF_BH, gBh + koff);
        CP_ASYNC16(d + OFF_BL, gBl + koff);
        CP_COMMIT();
    }

    // ldmatrix lane coords (row within 16x16 tile, logical k-chunk 0/1)
    const int ar  = (lane & 7) + ((lane >> 3) & 1) * 8;
    const int akl = (lane >> 4) & 1;                 // A logical chunk
    const int br  = (lane & 7) + ((lane >> 4) & 1) * 8;
    const int bkl = (lane >> 3) & 1;                 // B logical chunk

    int slot = 0;
    for (int s = 0; s < NSTAGE; s++) {
        if (s + 1 < NSTAGE) { CP_WAIT1(); } else { CP_WAIT0(); }
        __syncthreads();

        // prefetch stage s+2 into slot (s+2)%3 (safe: all threads past s-1)
        if (s + 2 < NSTAGE) {
            int koff = (s + 2) * 16;
            int ps = slot + 2; if (ps >= 3) ps -= 3;
            uint32_t d = sdst + ps * STAGE_BYTES;
            CP_ASYNC16(d,          gAh + koff);
            CP_ASYNC16(d + OFF_AL, gAl + koff);
            CP_ASYNC16(d + OFF_BH, gBh + koff);
            CP_ASYNC16(d + OFF_BL, gBl + koff);
            CP_COMMIT();
        }

        const uint32_t s0 = sb + slot * STAGE_BYTES;

        uint32_t ahf[4][4], alf[4][4], bhf[4][2], blf[4][2];
        #pragma unroll
        for (int mt = 0; mt < 4; mt++) {
            int row = wm * 64 + mt * 16 + ar;
            uint32_t ad = s0 + row * SROW + ((akl ^ ((row >> 2) & 1)) * 16);
            LDSM4(ahf[mt], ad);
            LDSM4(alf[mt], ad + OFF_AL);
        }
        #pragma unroll
        for (int h = 0; h < 2; h++) {
            int row = wn * 32 + h * 16 + br;
            uint32_t bd = s0 + OFF_BH + row * SROW + ((bkl ^ ((row >> 2) & 1)) * 16);
            uint32_t r[4];
            LDSM4(r, bd);
            bhf[h * 2][0] = r[0]; bhf[h * 2][1] = r[1];
            bhf[h * 2 + 1][0] = r[2]; bhf[h * 2 + 1][1] = r[3];
            LDSM4(r, bd + OFF_AL);   // BL = BH + 4096
            blf[h * 2][0] = r[0]; blf[h * 2][1] = r[1];
            blf[h * 2 + 1][0] = r[2]; blf[h * 2 + 1][1] = r[3];
        }

        #pragma unroll
        for (int mt = 0; mt < 4; mt++)
            #pragma unroll
            for (int nt = 0; nt < 4; nt++) {
                MMA16816(acc[mt][nt], ahf[mt], bhf[nt]);
                MMA16816(acc[mt][nt], alf[mt], bhf[nt]);
                MMA16816(acc[mt][nt], ahf[mt], blf[nt]);
            }

        if (++slot == 3) slot = 0;
    }

    #pragma unroll
    for (int mt = 0; mt < 4; mt++) {
        int rbase = bm + wm * 64 + mt * 16 + (lane >> 2);
        #pragma unroll
        for (int half = 0; half < 2; half++) {
            int r = rbase + half * 8;
            if (r >= M) continue;
            float dv = (EMODE == 1) ? dinv[r] : 0.f;
            #pragma unroll
            for (int nt = 0; nt < 4; nt++) {
                int c = bn + wn * 32 + nt * 8 + (lane & 3) * 2;
                float x = acc[mt][nt][half * 2];
                float y = acc[mt][nt][half * 2 + 1];
                if (EMODE == 1) {
                    x *= dv; y *= dv;
                    *reinterpret_cast<float2*>(&C[(size_t)r * N + c]) = make_float2(x, y);
                } else if (EMODE == 2) {
                    x = fmaxf(x + obias[c], 0.f);
                    y = fmaxf(y + obias[c + 1], 0.f);
                    uint32_t hi, lo;
                    split_pair(x, y, hi, lo);
                    *reinterpret_cast<uint32_t*>(&Oh[(size_t)r * DF + c]) = hi;
                    *reinterpret_cast<uint32_t*>(&Ol[(size_t)r * DF + c]) = lo;
                } else {
                    x += obias[c];
                    y += obias[c + 1];
                    *reinterpret_cast<float2*>(&C[(size_t)r * N + c]) = make_float2(x, y);
                }
            }
        }
    }
}

// ---------------------------------------------------------------------------
// row softmax over 128 cols: one warp per row
// ---------------------------------------------------------------------------
__global__ __launch_bounds__(256) void softmax128(
    const float* __restrict__ in, float* __restrict__ out, int n)
{
    int row  = (blockIdx.x * blockDim.x + threadIdx.x) >> 5;
    int lane = threadIdx.x & 31;
    if (row >= n) return;
    float4 v = reinterpret_cast<const float4*>(in + (size_t)row * 128)[lane];
    float m = fmaxf(fmaxf(v.x, v.y), fmaxf(v.z, v.w));
    #pragma unroll
    for (int o = 16; o > 0; o >>= 1) m = fmaxf(m, __shfl_xor_sync(0xFFFFFFFFu, m, o));
    float e0 = expf(v.x - m), e1 = expf(v.y - m), e2 = expf(v.z - m), e3 = expf(v.w - m);
    float s = e0 + e1 + e2 + e3;
    #pragma unroll
    for (int o = 16; o > 0; o >>= 1) s += __shfl_xor_sync(0xFFFFFFFFu, s, o);
    float inv = 1.0f / s;
    reinterpret_cast<float4*>(out + (size_t)row * 128)[lane] =
        make_float4(e0 * inv, e1 * inv, e2 * inv, e3 * inv);
}

// ---------------------------------------------------------------------------
// kernel_launch — inputs: x, edge_index, W1, b1, W2, b2, Wf1, bf1, Wf2, bf2
// ---------------------------------------------------------------------------
extern "C" void kernel_launch(void* const* d_in, const int* in_sizes, int n_in,
                              void* d_out, int out_size)
{
    const float* x   = (const float*)d_in[0];
    const int*   ei  = (const int*)  d_in[1];
    const float* W1  = (const float*)d_in[2];
    const float* b1  = (const float*)d_in[3];
    const float* W2  = (const float*)d_in[4];
    const float* b2  = (const float*)d_in[5];
    const float* Wf1 = (const float*)d_in[6];
    const float* bf1 = (const float*)d_in[7];
    const float* Wf2 = (const float*)d_in[8];
    const float* bf2 = (const float*)d_in[9];

    const int NV = in_sizes[0] / DF;   // 20000
    const int E  = in_sizes[1] / 2;    // 320000
    const int* srcIdx = ei;
    const int* dstIdx = ei + E;

    float *bufA, *dinv;
    __nv_bfloat16 *ah, *al, *bh, *bl, *wh, *wl;
    int *cnt, *rowptr, *cursor, *col;
    cudaGetSymbolAddress((void**)&bufA, g_bufA);
    cudaGetSymbolAddress((void**)&dinv, g_dinv);
    cudaGetSymbolAddress((void**)&ah, g_ah);
    cudaGetSymbolAddress((void**)&al, g_al);
    cudaGetSymbolAddress((void**)&bh, g_bh);
    cudaGetSymbolAddress((void**)&bl, g_bl);
    cudaGetSymbolAddress((void**)&wh, g_wh);
    cudaGetSymbolAddress((void**)&wl, g_wl);
    cudaGetSymbolAddress((void**)&cnt, g_cnt);
    cudaGetSymbolAddress((void**)&rowptr, g_rowptr);
    cudaGetSymbolAddress((void**)&cursor, g_cursor);
    cudaGetSymbolAddress((void**)&col, g_col);

    const size_t W1o = 0, W2o = 512 * 512, Wf1o = 2 * 512 * 512, Wf2o = 3 * 512 * 512;

    const int nb  = (NV + 255) / 256;
    const int eb  = (E + 255) / 256;
    const int gwb = (NV * 32 + 127) / 128;
    const int smb = (NV * 32 + 255) / 256;
    const int spb = (NV * 128 + 255) / 256;

    // CSR build (also produces dinv)
    zero_cnt   <<<nb, 256>>>(cnt, NV);
    hist_kernel<<<eb, 256>>>(cnt, dstIdx, E);
    scan_kernel<<<1, 256>>>(cnt, rowptr, cursor, dinv, NV);
    fill_kernel<<<eb, 256>>>(srcIdx, dstIdx, cursor, col, E);

    // weight convert
    wconv_kernel<<<(512 * 512 + 255) / 256, 256>>>(W1,  wh + W1o,  wl + W1o,  512, 512);
    wconv_kernel<<<(512 * 512 + 255) / 256, 256>>>(W2,  wh + W2o,  wl + W2o,  512, 512);
    wconv_kernel<<<(512 * 512 + 255) / 256, 256>>>(Wf1, wh + Wf1o, wl + Wf1o, 512, 512);
    wconv_kernel<<<(512 * 128 + 255) / 256, 256>>>(Wf2, wh + Wf2o, wl + Wf2o, 512, 128);

    dim3 blk(256);
    dim3 g512(4, (NV + 127) / 128);
    dim3 g128(1, (NV + 127) / 128);

    // layer 1
    split0_kernel<<<spb, 256>>>(x, ah, al, NV);
    gemm_bf16x3<1><<<g512, blk>>>(ah, al, wh + W1o, wl + W1o,
                                  bufA, nullptr, nullptr, nullptr, dinv, NV, 512);
    gather_csr<<<gwb, 128>>>(bufA, rowptr, col, dinv, b1, ah, al, NV);

    // layer 2
    gemm_bf16x3<1><<<g512, blk>>>(ah, al, wh + W2o, wl + W2o,
                                  bufA, nullptr, nullptr, nullptr, dinv, NV, 512);
    gather_csr<<<gwb, 128>>>(bufA, rowptr, col, dinv, b2, ah, al, NV);

    // fc1
    gemm_bf16x3<2><<<g512, blk>>>(ah, al, wh + Wf1o, wl + Wf1o,
                                  nullptr, bh, bl, bf1, nullptr, NV, 512);

    // fc2
    gemm_bf16x3<3><<<g128, blk>>>(bh, bl, wh + Wf2o, wl + Wf2o,
                                  bufA, nullptr, nullptr, bf2, nullptr, NV, 128);

    // softmax -> d_out
    softmax128<<<smb, 256>>>(bufA, (float*)d_out, NV);
}

// round 9
// speedup vs baseline: 2.3051x; 1.2318x over previous
#include <cuda_runtime.h>
#include <cuda_bf16.h>
#include <cstdint>

#define NMAX 20000
#define EMAX 400000
#define DF   512

// ---------------- scratch (static device globals; no allocs) ----------------
__device__ float g_bufA[(size_t)NMAX * DF];        // fp32 hs / logits
__device__ __nv_bfloat16 g_ah[(size_t)NMAX * DF];  // activation hi
__device__ __nv_bfloat16 g_al[(size_t)NMAX * DF];  // activation lo
__device__ __nv_bfloat16 g_bh[(size_t)NMAX * DF];  // fc1-out hi
__device__ __nv_bfloat16 g_bl[(size_t)NMAX * DF];  // fc1-out lo
__device__ __nv_bfloat16 g_wh[3 * 512 * 512 + 128 * 512]; // weights hi ([N][K])
__device__ __nv_bfloat16 g_wl[3 * 512 * 512 + 128 * 512]; // weights lo
__device__ float g_dinv[NMAX];
__device__ int   g_cnt[NMAX];
__device__ int   g_rowptr[NMAX + 1];
__device__ int   g_cursor[NMAX];
__device__ int   g_col[EMAX];

// ---------------------------------------------------------------------------
// helpers
// ---------------------------------------------------------------------------
__device__ __forceinline__ void split_pair(float x, float y, uint32_t& hi, uint32_t& lo) {
    __nv_bfloat162 h = __floats2bfloat162_rn(x, y);
    float rx = x - __bfloat162float(h.x);
    float ry = y - __bfloat162float(h.y);
    __nv_bfloat162 l = __floats2bfloat162_rn(rx, ry);
    hi = *reinterpret_cast<uint32_t*>(&h);
    lo = *reinterpret_cast<uint32_t*>(&l);
}

#define CP_ASYNC16(dst, src) \
    asm volatile("cp.async.cg.shared.global [%0], [%1], 16;" :: "r"(dst), "l"(src))
#define CP_COMMIT() asm volatile("cp.async.commit_group;")
#define CP_WAIT0()  asm volatile("cp.async.wait_group 0;")
#define CP_WAIT1()  asm volatile("cp.async.wait_group 1;")

#define LDSM4(R, addr) \
    asm volatile("ldmatrix.sync.aligned.m8n8.x4.shared.b16 {%0,%1,%2,%3}, [%4];" \
                 : "=r"((R)[0]), "=r"((R)[1]), "=r"((R)[2]), "=r"((R)[3]) : "r"(addr))

#define MMA16816(d, a, b) \
    asm volatile("mma.sync.aligned.m16n8k16.row.col.f32.bf16.bf16.f32 " \
                 "{%0,%1,%2,%3}, {%4,%5,%6,%7}, {%8,%9}, {%0,%1,%2,%3};" \
                 : "+f"((d)[0]), "+f"((d)[1]), "+f"((d)[2]), "+f"((d)[3]) \
                 : "r"((a)[0]), "r"((a)[1]), "r"((a)[2]), "r"((a)[3]), \
                   "r"((b)[0]), "r"((b)[1]))

// ---------------------------------------------------------------------------
// CSR build
// ---------------------------------------------------------------------------
__global__ void zero_cnt(int* cnt, int n) {
    int i = blockIdx.x * blockDim.x + threadIdx.x;
    if (i < n) cnt[i] = 0;
}
__global__ void hist_kernel(int* cnt, const int* __restrict__ dst, int E) {
    int e = blockIdx.x * blockDim.x + threadIdx.x;
    if (e < E) {
        int d = dst[e];
        if (d >= 0 && d < NMAX) atomicAdd(&cnt[d], 1);
    }
}
__global__ __launch_bounds__(256) void scan_kernel(
    const int* __restrict__ cnt, int* rowptr, int* cursor, float* dinv, int n)
{
    __shared__ int warpsum[8];
    const int tid  = threadIdx.x;
    const int lane = tid & 31;
    const int wrp  = tid >> 5;
    const int NT   = 256;
    const int per  = (n + NT - 1) / NT;
    const int begin = tid * per;
    const int stop  = min(begin + per, n);

    int local = 0;
    for (int i = begin; i < stop; i++) local += cnt[i];

    int v = local;
    #pragma unroll
    for (int o = 1; o < 32; o <<= 1) {
        int t = __shfl_up_sync(0xFFFFFFFFu, v, o);
        if (lane >= o) v += t;
    }
    if (lane == 31) warpsum[wrp] = v;
    __syncthreads();
    if (wrp == 0) {
        int w = (lane < 8) ? warpsum[lane] : 0;
        #pragma unroll
        for (int o = 1; o < 8; o <<= 1) {
            int t = __shfl_up_sync(0xFFFFFFFFu, w, o);
            if (lane >= o) w += t;
        }
        if (lane < 8) warpsum[lane] = w;
    }
    __syncthreads();
    int exclusive = v - local + ((wrp > 0) ? warpsum[wrp - 1] : 0);

    int run = exclusive;
    for (int i = begin; i < stop; i++) {
        rowptr[i] = run;
        cursor[i] = run;
        dinv[i]   = rsqrtf((float)cnt[i] + 1.0f);
        run += cnt[i];
    }
    if (tid == NT - 1) rowptr[n] = warpsum[7];
}
__global__ void fill_kernel(const int* __restrict__ src, const int* __restrict__ dst,
                            int* cursor, int* col, int E) {
    int e = blockIdx.x * blockDim.x + threadIdx.x;
    if (e < E) {
        int d = dst[e];
        if (d >= 0 && d < NMAX) {
            int pos = atomicAdd(&cursor[d], 1);
            if (pos >= 0 && pos < EMAX) col[pos] = src[e];
        }
    }
}

// ---------------------------------------------------------------------------
// weight convert: W [K][N] fp32 -> transposed hi/lo bf16 [N][K]
// ---------------------------------------------------------------------------
__global__ void wconv_kernel(const float* __restrict__ W,
                             __nv_bfloat16* __restrict__ oh,
                             __nv_bfloat16* __restrict__ ol, int K, int N) {
    int idx = blockIdx.x * blockDim.x + threadIdx.x;
    if (idx >= K * N) return;
    int n = idx / K, k = idx % K;
    float w = W[(size_t)k * N + n];
    __nv_bfloat16 h = __float2bfloat16_rn(w);
    float r = w - __bfloat162float(h);
    oh[idx] = h;
    ol[idx] = __float2bfloat16_rn(r);
}

// ---------------------------------------------------------------------------
// plain split for input x
// ---------------------------------------------------------------------------
__global__ void split0_kernel(const float* __restrict__ in,
                              __nv_bfloat16* __restrict__ oh,
                              __nv_bfloat16* __restrict__ ol, int M) {
    int idx = blockIdx.x * blockDim.x + threadIdx.x;
    if (idx >= M * (DF / 4)) return;
    int row = idx >> 7;
    int c = (idx & 127) * 4;
    float4 v = *reinterpret_cast<const float4*>(&in[(size_t)row * DF + c]);
    uint32_t h0, l0, h1, l1;
    split_pair(v.x, v.y, h0, l0);
    split_pair(v.z, v.w, h1, l1);
    *reinterpret_cast<uint2*>(&oh[(size_t)row * DF + c]) = make_uint2(h0, h1);
    *reinterpret_cast<uint2*>(&ol[(size_t)row * DF + c]) = make_uint2(l0, l1);
}

// ---------------------------------------------------------------------------
// CSR gather + fused GCN epilogue: one warp per node, 256-thread blocks.
// ---------------------------------------------------------------------------
__global__ __launch_bounds__(256) void gather_csr(
    const float* __restrict__ hs, const int* __restrict__ rowptr,
    const int* __restrict__ col, const float* __restrict__ dinv,
    const float* __restrict__ bias,
    __nv_bfloat16* __restrict__ oh, __nv_bfloat16* __restrict__ ol, int n)
{
    int node = (blockIdx.x * blockDim.x + threadIdx.x) >> 5;
    int lane = threadIdx.x & 31;
    if (node >= n) return;

    const float4* self = reinterpret_cast<const float4*>(hs + (size_t)node * DF);
    float4 acc[4];
    #pragma unroll
    for (int i = 0; i < 4; i++) acc[i] = self[lane + 32 * i];

    int p = rowptr[node];
    int e = rowptr[node + 1];
    if (p < 0) p = 0;
    if (e > EMAX) e = EMAX;

    while (p + 2 <= e) {
        int c0 = col[p], c1 = col[p + 1];
        const float4* r0 = reinterpret_cast<const float4*>(hs + (size_t)c0 * DF);
        const float4* r1 = reinterpret_cast<const float4*>(hs + (size_t)c1 * DF);
        float4 a0[4], a1[4];
        #pragma unroll
        for (int i = 0; i < 4; i++) a0[i] = r0[lane + 32 * i];
        #pragma unroll
        for (int i = 0; i < 4; i++) a1[i] = r1[lane + 32 * i];
        #pragma unroll
        for (int i = 0; i < 4; i++) {
            acc[i].x += a0[i].x + a1[i].x;
            acc[i].y += a0[i].y + a1[i].y;
            acc[i].z += a0[i].z + a1[i].z;
            acc[i].w += a0[i].w + a1[i].w;
        }
        p += 2;
    }
    if (p < e) {
        const float4* r0 = reinterpret_cast<const float4*>(hs + (size_t)col[p] * DF);
        #pragma unroll
        for (int i = 0; i < 4; i++) {
            float4 a = r0[lane + 32 * i];
            acc[i].x += a.x; acc[i].y += a.y; acc[i].z += a.z; acc[i].w += a.w;
        }
    }

    const float dv = dinv[node];
    const float4* bias4 = reinterpret_cast<const float4*>(bias);
    #pragma unroll
    for (int i = 0; i < 4; i++) {
        int f = lane + 32 * i;
        int c = f * 4;
        float4 bv = bias4[f];
        float x0 = fmaxf(acc[i].x * dv + bv.x, 0.f);
        float x1 = fmaxf(acc[i].y * dv + bv.y, 0.f);
        float x2 = fmaxf(acc[i].z * dv + bv.z, 0.f);
        float x3 = fmaxf(acc[i].w * dv + bv.w, 0.f);
        uint32_t h0, l0, h1, l1;
        split_pair(x0, x1, h0, l0);
        split_pair(x2, x3, h1, l1);
        *reinterpret_cast<uint2*>(&oh[(size_t)node * DF + c]) = make_uint2(h0, h1);
        *reinterpret_cast<uint2*>(&ol[(size_t)node * DF + c]) = make_uint2(l0, l1);
    }
}

// ---------------------------------------------------------------------------
// bf16x3 tensor-core GEMM — BM=64 x BN=128, 3-stage cp.async, XOR swizzle.
// 8 warps as 2(m) x 4(n); warp tile 32x32; acc[2][4][4] = 32 regs.
// Stage: A 64x16 hi+lo (4KB) + B 128x16 hi+lo (8KB) = 12KB; 3 stages = 36KB.
// __launch_bounds__(256,2) -> 2 CTAs/SM, 16 warps/SM.
//  EMODE 1: C = acc * dinv[row]
//  EMODE 2: r = relu(acc+obias); Oh/Ol = split(r)
//  EMODE 3: C = acc + obias
// ---------------------------------------------------------------------------
#define SROW 32
#define STAGE_BYTES 12288
#define OFF_AL 2048
#define OFF_BH 4096
#define OFF_BL 8192

template<int EMODE>
__global__ __launch_bounds__(256, 2) void gemm_bf16x3(
    const __nv_bfloat16* __restrict__ Ah, const __nv_bfloat16* __restrict__ Al,
    const __nv_bfloat16* __restrict__ Bh, const __nv_bfloat16* __restrict__ Bl,
    float* __restrict__ C,
    __nv_bfloat16* __restrict__ Oh, __nv_bfloat16* __restrict__ Ol,
    const float* __restrict__ obias, const float* __restrict__ dinv,
    int M, int N)
{
    __shared__ __align__(16) char smem[3 * STAGE_BYTES];

    const int tid  = threadIdx.x;
    const int lane = tid & 31;
    const int wid  = tid >> 5;
    const int wm   = wid >> 2;   // 0..1 (32 rows each)
    const int wn   = wid & 3;    // 0..3 (32 cols each)
    const int bm   = blockIdx.y * 64;
    const int bn   = blockIdx.x * 128;

    const uint32_t sb = (uint32_t)__cvta_generic_to_shared(smem);

    // loader coords
    const int lrow   = tid >> 1;           // B rows 0..127; A rows 0..63 (tid<128)
    const int lchunk = tid & 1;
    const int pchunk = lchunk ^ ((lrow >> 2) & 1);
    const int lce    = lchunk * 8;

    const int brow = bn + lrow;
    const __nv_bfloat16* gBh = Bh + (size_t)brow * DF + lce;
    const __nv_bfloat16* gBl = Bl + (size_t)brow * DF + lce;
    const uint32_t sdstB = sb + lrow * SROW + pchunk * 16;

    const bool aload = (tid < 128);
    const int arow = min(bm + lrow, M - 1);
    const __nv_bfloat16* gAh = Ah + (size_t)arow * DF + lce;
    const __nv_bfloat16* gAl = Al + (size_t)arow * DF + lce;
    const uint32_t sdstA = sb + lrow * SROW + pchunk * 16;

    float acc[2][4][4];
    #pragma unroll
    for (int i = 0; i < 2; i++)
        #pragma unroll
        for (int j = 0; j < 4; j++)
            #pragma unroll
            for (int k = 0; k < 4; k++) acc[i][j][k] = 0.f;

    const int NSTAGE = DF / 16;   // 32

    // prologue: stages 0,1 in flight (B first, then A — order perturbation)
    #pragma unroll
    for (int st = 0; st < 2; st++) {
        int koff = st * 16;
        uint32_t dA = sdstA + st * STAGE_BYTES;
        uint32_t dB = sdstB + st * STAGE_BYTES;
        CP_ASYNC16(dB + OFF_BH, gBh + koff);
        CP_ASYNC16(dB + OFF_BL, gBl + koff);
        if (aload) {
            CP_ASYNC16(dA,          gAh + koff);
            CP_ASYNC16(dA + OFF_AL, gAl + koff);
        }
        CP_COMMIT();
    }

    const int ar  = (lane & 7) + ((lane >> 3) & 1) * 8;
    const int akl = (lane >> 4) & 1;
    const int br  = (lane & 7) + ((lane >> 4) & 1) * 8;
    const int bkl = (lane >> 3) & 1;

    int slot = 0;
    for (int s = 0; s < NSTAGE; s++) {
        if (s + 1 < NSTAGE) { CP_WAIT1(); } else { CP_WAIT0(); }
        __syncthreads();

        if (s + 2 < NSTAGE) {
            int koff = (s + 2) * 16;
            int ps = slot + 2; if (ps >= 3) ps -= 3;
            uint32_t dA = sdstA + ps * STAGE_BYTES;
            uint32_t dB = sdstB + ps * STAGE_BYTES;
            CP_ASYNC16(dB + OFF_BH, gBh + koff);
            CP_ASYNC16(dB + OFF_BL, gBl + koff);
            if (aload) {
                CP_ASYNC16(dA,          gAh + koff);
                CP_ASYNC16(dA + OFF_AL, gAl + koff);
            }
            CP_COMMIT();
        }

        const uint32_t s0 = sb + slot * STAGE_BYTES;

        uint32_t ahf[2][4], alf[2][4], bhf[4][2], blf[4][2];
        #pragma unroll
        for (int mt = 0; mt < 2; mt++) {
            int row = wm * 32 + mt * 16 + ar;
            uint32_t ad = s0 + row * SROW + ((akl ^ ((row >> 2) & 1)) * 16);
            LDSM4(ahf[mt], ad);
            LDSM4(alf[mt], ad + OFF_AL);
        }
        #pragma unroll
        for (int h = 0; h < 2; h++) {
            int row = wn * 32 + h * 16 + br;
            uint32_t bd = s0 + OFF_BH + row * SROW + ((bkl ^ ((row >> 2) & 1)) * 16);
            uint32_t r[4];
            LDSM4(r, bd);
            bhf[h * 2][0] = r[0]; bhf[h * 2][1] = r[1];
            bhf[h * 2 + 1][0] = r[2]; bhf[h * 2 + 1][1] = r[3];
            LDSM4(r, bd + (OFF_BL - OFF_BH));
            blf[h * 2][0] = r[0]; blf[h * 2][1] = r[1];
            blf[h * 2 + 1][0] = r[2]; blf[h * 2 + 1][1] = r[3];
        }

        #pragma unroll
        for (int mt = 0; mt < 2; mt++)
            #pragma unroll
            for (int nt = 0; nt < 4; nt++) {
                MMA16816(acc[mt][nt], ahf[mt], bhf[nt]);
                MMA16816(acc[mt][nt], alf[mt], bhf[nt]);
                MMA16816(acc[mt][nt], ahf[mt], blf[nt]);
            }

        if (++slot == 3) slot = 0;
    }

    #pragma unroll
    for (int mt = 0; mt < 2; mt++) {
        int rbase = bm + wm * 32 + mt * 16 + (lane >> 2);
        #pragma unroll
        for (int half = 0; half < 2; half++) {
            int r = rbase + half * 8;
            if (r >= M) continue;
            float dv = (EMODE == 1) ? dinv[r] : 0.f;
            #pragma unroll
            for (int nt = 0; nt < 4; nt++) {
                int c = bn + wn * 32 + nt * 8 + (lane & 3) * 2;
                float x = acc[mt][nt][half * 2];
                float y = acc[mt][nt][half * 2 + 1];
                if (EMODE == 1) {
                    x *= dv; y *= dv;
                    *reinterpret_cast<float2*>(&C[(size_t)r * N + c]) = make_float2(x, y);
                } else if (EMODE == 2) {
                    x = fmaxf(x + obias[c], 0.f);
                    y = fmaxf(y + obias[c + 1], 0.f);
                    uint32_t hi, lo;
                    split_pair(x, y, hi, lo);
                    *reinterpret_cast<uint32_t*>(&Oh[(size_t)r * DF + c]) = hi;
                    *reinterpret_cast<uint32_t*>(&Ol[(size_t)r * DF + c]) = lo;
                } else {
                    x += obias[c];
                    y += obias[c + 1];
                    *reinterpret_cast<float2*>(&C[(size_t)r * N + c]) = make_float2(x, y);
                }
            }
        }
    }
}

// ---------------------------------------------------------------------------
// row softmax over 128 cols: one warp per row
// ---------------------------------------------------------------------------
__global__ __launch_bounds__(256) void softmax128(
    const float* __restrict__ in, float* __restrict__ out, int n)
{
    int row  = (blockIdx.x * blockDim.x + threadIdx.x) >> 5;
    int lane = threadIdx.x & 31;
    if (row >= n) return;
    float4 v = reinterpret_cast<const float4*>(in + (size_t)row * 128)[lane];
    float m = fmaxf(fmaxf(v.x, v.y), fmaxf(v.z, v.w));
    #pragma unroll
    for (int o = 16; o > 0; o >>= 1) m = fmaxf(m, __shfl_xor_sync(0xFFFFFFFFu, m, o));
    float e0 = expf(v.x - m), e1 = expf(v.y - m), e2 = expf(v.z - m), e3 = expf(v.w - m);
    float s = e0 + e1 + e2 + e3;
    #pragma unroll
    for (int o = 16; o > 0; o >>= 1) s += __shfl_xor_sync(0xFFFFFFFFu, s, o);
    float inv = 1.0f / s;
    reinterpret_cast<float4*>(out + (size_t)row * 128)[lane] =
        make_float4(e0 * inv, e1 * inv, e2 * inv, e3 * inv);
}

// ---------------------------------------------------------------------------
// kernel_launch — inputs: x, edge_index, W1, b1, W2, b2, Wf1, bf1, Wf2, bf2
// ---------------------------------------------------------------------------
extern "C" void kernel_launch(void* const* d_in, const int* in_sizes, int n_in,
                              void* d_out, int out_size)
{
    const float* x   = (const float*)d_in[0];
    const int*   ei  = (const int*)  d_in[1];
    const float* W1  = (const float*)d_in[2];
    const float* b1  = (const float*)d_in[3];
    const float* W2  = (const float*)d_in[4];
    const float* b2  = (const float*)d_in[5];
    const float* Wf1 = (const float*)d_in[6];
    const float* bf1 = (const float*)d_in[7];
    const float* Wf2 = (const float*)d_in[8];
    const float* bf2 = (const float*)d_in[9];

    const int NV = in_sizes[0] / DF;   // 20000
    const int E  = in_sizes[1] / 2;    // 320000
    const int* srcIdx = ei;
    const int* dstIdx = ei + E;

    float *bufA, *dinv;
    __nv_bfloat16 *ah, *al, *bh, *bl, *wh, *wl;
    int *cnt, *rowptr, *cursor, *col;
    cudaGetSymbolAddress((void**)&bufA, g_bufA);
    cudaGetSymbolAddress((void**)&dinv, g_dinv);
    cudaGetSymbolAddress((void**)&ah, g_ah);
    cudaGetSymbolAddress((void**)&al, g_al);
    cudaGetSymbolAddress((void**)&bh, g_bh);
    cudaGetSymbolAddress((void**)&bl, g_bl);
    cudaGetSymbolAddress((void**)&wh, g_wh);
    cudaGetSymbolAddress((void**)&wl, g_wl);
    cudaGetSymbolAddress((void**)&cnt, g_cnt);
    cudaGetSymbolAddress((void**)&rowptr, g_rowptr);
    cudaGetSymbolAddress((void**)&cursor, g_cursor);
    cudaGetSymbolAddress((void**)&col, g_col);

    const size_t W1o = 0, W2o = 512 * 512, Wf1o = 2 * 512 * 512, Wf2o = 3 * 512 * 512;

    const int nb  = (NV + 255) / 256;
    const int eb  = (E + 255) / 256;
    const int gwb = (NV * 32 + 255) / 256;
    const int smb = (NV * 32 + 255) / 256;
    const int spb = (NV * 128 + 255) / 256;

    // CSR build (also produces dinv)
    zero_cnt   <<<nb, 256>>>(cnt, NV);
    hist_kernel<<<eb, 256>>>(cnt, dstIdx, E);
    scan_kernel<<<1, 256>>>(cnt, rowptr, cursor, dinv, NV);
    fill_kernel<<<eb, 256>>>(srcIdx, dstIdx, cursor, col, E);

    // weight convert
    wconv_kernel<<<(512 * 512 + 255) / 256, 256>>>(W1,  wh + W1o,  wl + W1o,  512, 512);
    wconv_kernel<<<(512 * 512 + 255) / 256, 256>>>(W2,  wh + W2o,  wl + W2o,  512, 512);
    wconv_kernel<<<(512 * 512 + 255) / 256, 256>>>(Wf1, wh + Wf1o, wl + Wf1o, 512, 512);
    wconv_kernel<<<(512 * 128 + 255) / 256, 256>>>(Wf2, wh + Wf2o, wl + Wf2o, 512, 128);

    dim3 blk(256);
    dim3 g512(4, (NV + 63) / 64);
    dim3 g128(1, (NV + 63) / 64);

    // layer 1
    split0_kernel<<<spb, 256>>>(x, ah, al, NV);
    gemm_bf16x3<1><<<g512, blk>>>(ah, al, wh + W1o, wl + W1o,
                                  bufA, nullptr, nullptr, nullptr, dinv, NV, 512);
    gather_csr<<<gwb, 256>>>(bufA, rowptr, col, dinv, b1, ah, al, NV);

    // layer 2
    gemm_bf16x3<1><<<g512, blk>>>(ah, al, wh + W2o, wl + W2o,
                                  bufA, nullptr, nullptr, nullptr, dinv, NV, 512);
    gather_csr<<<gwb, 256>>>(bufA, rowptr, col, dinv, b2, ah, al, NV);

    // fc1
    gemm_bf16x3<2><<<g512, blk>>>(ah, al, wh + Wf1o, wl + Wf1o,
                                  nullptr, bh, bl, bf1, nullptr, NV, 512);

    // fc2
    gemm_bf16x3<3><<<g128, blk>>>(bh, bl, wh + Wf2o, wl + Wf2o,
                                  bufA, nullptr, nullptr, bf2, nullptr, NV, 128);

    // softmax -> d_out
    softmax128<<<smb, 256>>>(bufA, (float*)d_out, NV);
}

// round 10
// speedup vs baseline: 2.4319x; 1.0550x over previous
#include <cuda_runtime.h>
#include <cuda_bf16.h>
#include <cstdint>

#define NMAX 20000
#define EMAX 400000
#define DF   512

// ---------------- scratch (static device globals; no allocs) ----------------
__device__ float g_bufA[(size_t)NMAX * DF];        // fp32 hs / logits
__device__ __nv_bfloat16 g_ah[(size_t)NMAX * DF];  // activation hi
__device__ __nv_bfloat16 g_al[(size_t)NMAX * DF];  // activation lo
__device__ __nv_bfloat16 g_bh[(size_t)NMAX * DF];  // fc1-out hi
__device__ __nv_bfloat16 g_bl[(size_t)NMAX * DF];  // fc1-out lo
__device__ __nv_bfloat16 g_wh[3 * 512 * 512 + 128 * 512]; // weights hi ([N][K])
__device__ __nv_bfloat16 g_wl[3 * 512 * 512 + 128 * 512]; // weights lo
__device__ float g_dinv[NMAX];
__device__ int   g_cnt[NMAX];
__device__ int   g_rowptr[NMAX + 1];
__device__ int   g_cursor[NMAX];
__device__ int   g_col[EMAX];

// ---------------------------------------------------------------------------
// helpers
// ---------------------------------------------------------------------------
__device__ __forceinline__ void split_pair(float x, float y, uint32_t& hi, uint32_t& lo) {
    __nv_bfloat162 h = __floats2bfloat162_rn(x, y);
    float rx = x - __bfloat162float(h.x);
    float ry = y - __bfloat162float(h.y);
    __nv_bfloat162 l = __floats2bfloat162_rn(rx, ry);
    hi = *reinterpret_cast<uint32_t*>(&h);
    lo = *reinterpret_cast<uint32_t*>(&l);
}

#define CP_ASYNC16(dst, src) \
    asm volatile("cp.async.cg.shared.global [%0], [%1], 16;" :: "r"(dst), "l"(src))
#define CP_COMMIT() asm volatile("cp.async.commit_group;")
#define CP_WAIT0()  asm volatile("cp.async.wait_group 0;")
#define CP_WAIT1()  asm volatile("cp.async.wait_group 1;")

#define LDSM4(R, addr) \
    asm volatile("ldmatrix.sync.aligned.m8n8.x4.shared.b16 {%0,%1,%2,%3}, [%4];" \
                 : "=r"((R)[0]), "=r"((R)[1]), "=r"((R)[2]), "=r"((R)[3]) : "r"(addr))

#define MMA16816(d, a, b) \
    asm volatile("mma.sync.aligned.m16n8k16.row.col.f32.bf16.bf16.f32 " \
                 "{%0,%1,%2,%3}, {%4,%5,%6,%7}, {%8,%9}, {%0,%1,%2,%3};" \
                 : "+f"((d)[0]), "+f"((d)[1]), "+f"((d)[2]), "+f"((d)[3]) \
                 : "r"((a)[0]), "r"((a)[1]), "r"((a)[2]), "r"((a)[3]), \
                   "r"((b)[0]), "r"((b)[1]))

// ---------------------------------------------------------------------------
// CSR build
// ---------------------------------------------------------------------------
__global__ void zero_cnt(int* cnt, int n) {
    int i = blockIdx.x * blockDim.x + threadIdx.x;
    if (i < n) cnt[i] = 0;
}
__global__ void hist_kernel(int* cnt, const int* __restrict__ dst, int E) {
    int e = blockIdx.x * blockDim.x + threadIdx.x;
    if (e < E) {
        int d = dst[e];
        if (d >= 0 && d < NMAX) atomicAdd(&cnt[d], 1);
    }
}
__global__ __launch_bounds__(256) void scan_kernel(
    const int* __restrict__ cnt, int* rowptr, int* cursor, float* dinv, int n)
{
    __shared__ int warpsum[8];
    const int tid  = threadIdx.x;
    const int lane = tid & 31;
    const int wrp  = tid >> 5;
    const int NT   = 256;
    const int per  = (n + NT - 1) / NT;
    const int begin = tid * per;
    const int stop  = min(begin + per, n);

    int local = 0;
    for (int i = begin; i < stop; i++) local += cnt[i];

    int v = local;
    #pragma unroll
    for (int o = 1; o < 32; o <<= 1) {
        int t = __shfl_up_sync(0xFFFFFFFFu, v, o);
        if (lane >= o) v += t;
    }
    if (lane == 31) warpsum[wrp] = v;
    __syncthreads();
    if (wrp == 0) {
        int w = (lane < 8) ? warpsum[lane] : 0;
        #pragma unroll
        for (int o = 1; o < 8; o <<= 1) {
            int t = __shfl_up_sync(0xFFFFFFFFu, w, o);
            if (lane >= o) w += t;
        }
        if (lane < 8) warpsum[lane] = w;
    }
    __syncthreads();
    int exclusive = v - local + ((wrp > 0) ? warpsum[wrp - 1] : 0);

    int run = exclusive;
    for (int i = begin; i < stop; i++) {
        rowptr[i] = run;
        cursor[i] = run;
        dinv[i]   = rsqrtf((float)cnt[i] + 1.0f);
        run += cnt[i];
    }
    if (tid == NT - 1) rowptr[n] = warpsum[7];
}
__global__ void fill_kernel(const int* __restrict__ src, const int* __restrict__ dst,
                            int* cursor, int* col, int E) {
    int e = blockIdx.x * blockDim.x + threadIdx.x;
    if (e < E) {
        int d = dst[e];
        if (d >= 0 && d < NMAX) {
            int pos = atomicAdd(&cursor[d], 1);
            if (pos >= 0 && pos < EMAX) col[pos] = src[e];
        }
    }
}

// ---------------------------------------------------------------------------
// weight convert: W [K][N] fp32 -> transposed hi/lo bf16 [N][K]
// ---------------------------------------------------------------------------
__global__ void wconv_kernel(const float* __restrict__ W,
                             __nv_bfloat16* __restrict__ oh,
                             __nv_bfloat16* __restrict__ ol, int K, int N) {
    int idx = blockIdx.x * blockDim.x + threadIdx.x;
    if (idx >= K * N) return;
    int n = idx / K, k = idx % K;
    float w = W[(size_t)k * N + n];
    __nv_bfloat16 h = __float2bfloat16_rn(w);
    float r = w - __bfloat162float(h);
    oh[idx] = h;
    ol[idx] = __float2bfloat16_rn(r);
}

// ---------------------------------------------------------------------------
// plain split for input x
// ---------------------------------------------------------------------------
__global__ void split0_kernel(const float* __restrict__ in,
                              __nv_bfloat16* __restrict__ oh,
                              __nv_bfloat16* __restrict__ ol, int M) {
    int idx = blockIdx.x * blockDim.x + threadIdx.x;
    if (idx >= M * (DF / 4)) return;
    int row = idx >> 7;
    int c = (idx & 127) * 4;
    float4 v = *reinterpret_cast<const float4*>(&in[(size_t)row * DF + c]);
    uint32_t h0, l0, h1, l1;
    split_pair(v.x, v.y, h0, l0);
    split_pair(v.z, v.w, h1, l1);
    *reinterpret_cast<uint2*>(&oh[(size_t)row * DF + c]) = make_uint2(h0, h1);
    *reinterpret_cast<uint2*>(&ol[(size_t)row * DF + c]) = make_uint2(l0, l1);
}

// ---------------------------------------------------------------------------
// CSR gather + fused GCN epilogue: one warp per node, 256-thread blocks.
// ---------------------------------------------------------------------------
__global__ __launch_bounds__(256) void gather_csr(
    const float* __restrict__ hs, const int* __restrict__ rowptr,
    const int* __restrict__ col, const float* __restrict__ dinv,
    const float* __restrict__ bias,
    __nv_bfloat16* __restrict__ oh, __nv_bfloat16* __restrict__ ol, int n)
{
    int node = (blockIdx.x * blockDim.x + threadIdx.x) >> 5;
    int lane = threadIdx.x & 31;
    if (node >= n) return;

    const float4* self = reinterpret_cast<const float4*>(hs + (size_t)node * DF);
    float4 acc[4];
    #pragma unroll
    for (int i = 0; i < 4; i++) acc[i] = self[lane + 32 * i];

    int p = rowptr[node];
    int e = rowptr[node + 1];
    if (p < 0) p = 0;
    if (e > EMAX) e = EMAX;

    while (p + 2 <= e) {
        int c0 = col[p], c1 = col[p + 1];
        const float4* r0 = reinterpret_cast<const float4*>(hs + (size_t)c0 * DF);
        const float4* r1 = reinterpret_cast<const float4*>(hs + (size_t)c1 * DF);
        float4 a0[4], a1[4];
        #pragma unroll
        for (int i = 0; i < 4; i++) a0[i] = r0[lane + 32 * i];
        #pragma unroll
        for (int i = 0; i < 4; i++) a1[i] = r1[lane + 32 * i];
        #pragma unroll
        for (int i = 0; i < 4; i++) {
            acc[i].x += a0[i].x + a1[i].x;
            acc[i].y += a0[i].y + a1[i].y;
            acc[i].z += a0[i].z + a1[i].z;
            acc[i].w += a0[i].w + a1[i].w;
        }
        p += 2;
    }
    if (p < e) {
        const float4* r0 = reinterpret_cast<const float4*>(hs + (size_t)col[p] * DF);
        #pragma unroll
        for (int i = 0; i < 4; i++) {
            float4 a = r0[lane + 32 * i];
            acc[i].x += a.x; acc[i].y += a.y; acc[i].z += a.z; acc[i].w += a.w;
        }
    }

    const float dv = dinv[node];
    const float4* bias4 = reinterpret_cast<const float4*>(bias);
    #pragma unroll
    for (int i = 0; i < 4; i++) {
        int f = lane + 32 * i;
        int c = f * 4;
        float4 bv = bias4[f];
        float x0 = fmaxf(acc[i].x * dv + bv.x, 0.f);
        float x1 = fmaxf(acc[i].y * dv + bv.y, 0.f);
        float x2 = fmaxf(acc[i].z * dv + bv.z, 0.f);
        float x3 = fmaxf(acc[i].w * dv + bv.w, 0.f);
        uint32_t h0, l0, h1, l1;
        split_pair(x0, x1, h0, l0);
        split_pair(x2, x3, h1, l1);
        *reinterpret_cast<uint2*>(&oh[(size_t)node * DF + c]) = make_uint2(h0, h1);
        *reinterpret_cast<uint2*>(&ol[(size_t)node * DF + c]) = make_uint2(l0, l1);
    }
}

// ---------------------------------------------------------------------------
// bf16x3 tensor-core GEMM — BM=64 x BN=128, 3-stage cp.async, XOR swizzle.
// 8 warps as 2(m) x 4(n); warp tile 32x32; acc[2][4][4] = 32 regs.
// Stage: A 64x16 hi+lo (4KB) + B 128x16 hi+lo (8KB) = 12KB; 3 stages = 36KB.
// __launch_bounds__(256,3) -> 3 CTAs/SM target (85-reg cap), 24 warps/SM.
//  EMODE 1: C = acc * dinv[row]
//  EMODE 2: r = relu(acc+obias); Oh/Ol = split(r)
//  EMODE 3: C = acc + obias
// ---------------------------------------------------------------------------
#define SROW 32
#define STAGE_BYTES 12288
#define OFF_AL 2048
#define OFF_BH 4096
#define OFF_BL 8192

template<int EMODE>
__global__ __launch_bounds__(256, 3) void gemm_bf16x3(
    const __nv_bfloat16* __restrict__ Ah, const __nv_bfloat16* __restrict__ Al,
    const __nv_bfloat16* __restrict__ Bh, const __nv_bfloat16* __restrict__ Bl,
    float* __restrict__ C,
    __nv_bfloat16* __restrict__ Oh, __nv_bfloat16* __restrict__ Ol,
    const float* __restrict__ obias, const float* __restrict__ dinv,
    int M, int N)
{
    __shared__ __align__(16) char smem[3 * STAGE_BYTES];

    const int tid  = threadIdx.x;
    const int lane = tid & 31;
    const int wid  = tid >> 5;
    const int wm   = wid >> 2;   // 0..1 (32 rows each)
    const int wn   = wid & 3;    // 0..3 (32 cols each)
    const int bm   = blockIdx.y * 64;
    const int bn   = blockIdx.x * 128;

    const uint32_t sb = (uint32_t)__cvta_generic_to_shared(smem);

    // loader coords
    const int lrow   = tid >> 1;           // B rows 0..127; A rows 0..63 (tid<128)
    const int lchunk = tid & 1;
    const int pchunk = lchunk ^ ((lrow >> 2) & 1);
    const int lce    = lchunk * 8;

    const int brow = bn + lrow;
    const __nv_bfloat16* gBh = Bh + (size_t)brow * DF + lce;
    const __nv_bfloat16* gBl = Bl + (size_t)brow * DF + lce;
    const uint32_t sdstB = sb + lrow * SROW + pchunk * 16;

    const bool aload = (tid < 128);
    const int arow = min(bm + lrow, M - 1);
    const __nv_bfloat16* gAh = Ah + (size_t)arow * DF + lce;
    const __nv_bfloat16* gAl = Al + (size_t)arow * DF + lce;
    const uint32_t sdstA = sb + lrow * SROW + pchunk * 16;

    float acc[2][4][4];
    #pragma unroll
    for (int i = 0; i < 2; i++)
        #pragma unroll
        for (int j = 0; j < 4; j++)
            #pragma unroll
            for (int k = 0; k < 4; k++) acc[i][j][k] = 0.f;

    const int NSTAGE = DF / 16;   // 32

    // prologue: stages 0,1 in flight
    #pragma unroll
    for (int st = 0; st < 2; st++) {
        int koff = st * 16;
        uint32_t dA = sdstA + st * STAGE_BYTES;
        uint32_t dB = sdstB + st * STAGE_BYTES;
        CP_ASYNC16(dB + OFF_BH, gBh + koff);
        CP_ASYNC16(dB + OFF_BL, gBl + koff);
        if (aload) {
            CP_ASYNC16(dA,          gAh + koff);
            CP_ASYNC16(dA + OFF_AL, gAl + koff);
        }
        CP_COMMIT();
    }

    const int ar  = (lane & 7) + ((lane >> 3) & 1) * 8;
    const int akl = (lane >> 4) & 1;
    const int br  = (lane & 7) + ((lane >> 4) & 1) * 8;
    const int bkl = (lane >> 3) & 1;

    int slot = 0;
    for (int s = 0; s < NSTAGE; s++) {
        if (s + 1 < NSTAGE) { CP_WAIT1(); } else { CP_WAIT0(); }
        __syncthreads();

        if (s + 2 < NSTAGE) {
            int koff = (s + 2) * 16;
            int ps = slot + 2; if (ps >= 3) ps -= 3;
            uint32_t dA = sdstA + ps * STAGE_BYTES;
            uint32_t dB = sdstB + ps * STAGE_BYTES;
            CP_ASYNC16(dB + OFF_BH, gBh + koff);
            CP_ASYNC16(dB + OFF_BL, gBl + koff);
            if (aload) {
                CP_ASYNC16(dA,          gAh + koff);
                CP_ASYNC16(dA + OFF_AL, gAl + koff);
            }
            CP_COMMIT();
        }

        const uint32_t s0 = sb + slot * STAGE_BYTES;

        uint32_t ahf[2][4], alf[2][4], bhf[4][2], blf[4][2];
        #pragma unroll
        for (int mt = 0; mt < 2; mt++) {
            int row = wm * 32 + mt * 16 + ar;
            uint32_t ad = s0 + row * SROW + ((akl ^ ((row >> 2) & 1)) * 16);
            LDSM4(ahf[mt], ad);
            LDSM4(alf[mt], ad + OFF_AL);
        }
        #pragma unroll
        for (int h = 0; h < 2; h++) {
            int row = wn * 32 + h * 16 + br;
            uint32_t bd = s0 + OFF_BH + row * SROW + ((bkl ^ ((row >> 2) & 1)) * 16);
            uint32_t r[4];
            LDSM4(r, bd);
            bhf[h * 2][0] = r[0]; bhf[h * 2][1] = r[1];
            bhf[h * 2 + 1][0] = r[2]; bhf[h * 2 + 1][1] = r[3];
            LDSM4(r, bd + (OFF_BL - OFF_BH));
            blf[h * 2][0] = r[0]; blf[h * 2][1] = r[1];
            blf[h * 2 + 1][0] = r[2]; blf[h * 2 + 1][1] = r[3];
        }

        #pragma unroll
        for (int mt = 0; mt < 2; mt++)
            #pragma unroll
            for (int nt = 0; nt < 4; nt++) {
                MMA16816(acc[mt][nt], ahf[mt], bhf[nt]);
                MMA16816(acc[mt][nt], alf[mt], bhf[nt]);
                MMA16816(acc[mt][nt], ahf[mt], blf[nt]);
            }

        if (++slot == 3) slot = 0;
    }

    #pragma unroll
    for (int mt = 0; mt < 2; mt++) {
        int rbase = bm + wm * 32 + mt * 16 + (lane >> 2);
        #pragma unroll
        for (int half = 0; half < 2; half++) {
            int r = rbase + half * 8;
            if (r >= M) continue;
            float dv = (EMODE == 1) ? dinv[r] : 0.f;
            #pragma unroll
            for (int nt = 0; nt < 4; nt++) {
                int c = bn + wn * 32 + nt * 8 + (lane & 3) * 2;
                float x = acc[mt][nt][half * 2];
                float y = acc[mt][nt][half * 2 + 1];
                if (EMODE == 1) {
                    x *= dv; y *= dv;
                    *reinterpret_cast<float2*>(&C[(size_t)r * N + c]) = make_float2(x, y);
                } else if (EMODE == 2) {
                    x = fmaxf(x + obias[c], 0.f);
                    y = fmaxf(y + obias[c + 1], 0.f);
                    uint32_t hi, lo;
                    split_pair(x, y, hi, lo);
                    *reinterpret_cast<uint32_t*>(&Oh[(size_t)r * DF + c]) = hi;
                    *reinterpret_cast<uint32_t*>(&Ol[(size_t)r * DF + c]) = lo;
                } else {
                    x += obias[c];
                    y += obias[c + 1];
                    *reinterpret_cast<float2*>(&C[(size_t)r * N + c]) = make_float2(x, y);
                }
            }
        }
    }
}

// ---------------------------------------------------------------------------
// row softmax over 128 cols: one warp per row
// ---------------------------------------------------------------------------
__global__ __launch_bounds__(256) void softmax128(
    const float* __restrict__ in, float* __restrict__ out, int n)
{
    int row  = (blockIdx.x * blockDim.x + threadIdx.x) >> 5;
    int lane = threadIdx.x & 31;
    if (row >= n) return;
    float4 v = reinterpret_cast<const float4*>(in + (size_t)row * 128)[lane];
    float m = fmaxf(fmaxf(v.x, v.y), fmaxf(v.z, v.w));
    #pragma unroll
    for (int o = 16; o > 0; o >>= 1) m = fmaxf(m, __shfl_xor_sync(0xFFFFFFFFu, m, o));
    float e0 = expf(v.x - m), e1 = expf(v.y - m), e2 = expf(v.z - m), e3 = expf(v.w - m);
    float s = e0 + e1 + e2 + e3;
    #pragma unroll
    for (int o = 16; o > 0; o >>= 1) s += __shfl_xor_sync(0xFFFFFFFFu, s, o);
    float inv = 1.0f / s;
    reinterpret_cast<float4*>(out + (size_t)row * 128)[lane] =
        make_float4(e0 * inv, e1 * inv, e2 * inv, e3 * inv);
}

// ---------------------------------------------------------------------------
// kernel_launch — inputs: x, edge_index, W1, b1, W2, b2, Wf1, bf1, Wf2, bf2
// ---------------------------------------------------------------------------
extern "C" void kernel_launch(void* const* d_in, const int* in_sizes, int n_in,
                              void* d_out, int out_size)
{
    const float* x   = (const float*)d_in[0];
    const int*   ei  = (const int*)  d_in[1];
    const float* W1  = (const float*)d_in[2];
    const float* b1  = (const float*)d_in[3];
    const float* W2  = (const float*)d_in[4];
    const float* b2  = (const float*)d_in[5];
    const float* Wf1 = (const float*)d_in[6];
    const float* bf1 = (const float*)d_in[7];
    const float* Wf2 = (const float*)d_in[8];
    const float* bf2 = (const float*)d_in[9];

    const int NV = in_sizes[0] / DF;   // 20000
    const int E  = in_sizes[1] / 2;    // 320000
    const int* srcIdx = ei;
    const int* dstIdx = ei + E;

    float *bufA, *dinv;
    __nv_bfloat16 *ah, *al, *bh, *bl, *wh, *wl;
    int *cnt, *rowptr, *cursor, *col;
    cudaGetSymbolAddress((void**)&bufA, g_bufA);
    cudaGetSymbolAddress((void**)&dinv, g_dinv);
    cudaGetSymbolAddress((void**)&ah, g_ah);
    cudaGetSymbolAddress((void**)&al, g_al);
    cudaGetSymbolAddress((void**)&bh, g_bh);
    cudaGetSymbolAddress((void**)&bl, g_bl);
    cudaGetSymbolAddress((void**)&wh, g_wh);
    cudaGetSymbolAddress((void**)&wl, g_wl);
    cudaGetSymbolAddress((void**)&cnt, g_cnt);
    cudaGetSymbolAddress((void**)&rowptr, g_rowptr);
    cudaGetSymbolAddress((void**)&cursor, g_cursor);
    cudaGetSymbolAddress((void**)&col, g_col);

    const size_t W1o = 0, W2o = 512 * 512, Wf1o = 2 * 512 * 512, Wf2o = 3 * 512 * 512;

    const int nb  = (NV + 255) / 256;
    const int eb  = (E + 255) / 256;
    const int gwb = (NV * 32 + 255) / 256;
    const int smb = (NV * 32 + 255) / 256;
    const int spb = (NV * 128 + 255) / 256;

    // CSR build (also produces dinv)
    zero_cnt   <<<nb, 256>>>(cnt, NV);
    hist_kernel<<<eb, 256>>>(cnt, dstIdx, E);
    scan_kernel<<<1, 256>>>(cnt, rowptr, cursor, dinv, NV);
    fill_kernel<<<eb, 256>>>(srcIdx, dstIdx, cursor, col, E);

    // weight convert
    wconv_kernel<<<(512 * 512 + 255) / 256, 256>>>(W1,  wh + W1o,  wl + W1o,  512, 512);
    wconv_kernel<<<(512 * 512 + 255) / 256, 256>>>(W2,  wh + W2o,  wl + W2o,  512, 512);
    wconv_kernel<<<(512 * 512 + 255) / 256, 256>>>(Wf1, wh + Wf1o, wl + Wf1o, 512, 512);
    wconv_kernel<<<(512 * 128 + 255) / 256, 256>>>(Wf2, wh + Wf2o, wl + Wf2o, 512, 128);

    dim3 blk(256);
    dim3 g512(4, (NV + 63) / 64);
    dim3 g128(1, (NV + 63) / 64);

    // layer 1
    split0_kernel<<<spb, 256>>>(x, ah, al, NV);
    gemm_bf16x3<1><<<g512, blk>>>(ah, al, wh + W1o, wl + W1o,
                                  bufA, nullptr, nullptr, nullptr, dinv, NV, 512);
    gather_csr<<<gwb, 256>>>(bufA, rowptr, col, dinv, b1, ah, al, NV);

    // layer 2
    gemm_bf16x3<1><<<g512, blk>>>(ah, al, wh + W2o, wl + W2o,
                                  bufA, nullptr, nullptr, nullptr, dinv, NV, 512);
    gather_csr<<<gwb, 256>>>(bufA, rowptr, col, dinv, b2, ah, al, NV);

    // fc1
    gemm_bf16x3<2><<<g512, blk>>>(ah, al, wh + Wf1o, wl + Wf1o,
                                  nullptr, bh, bl, bf1, nullptr, NV, 512);

    // fc2
    gemm_bf16x3<3><<<g128, blk>>>(bh, bl, wh + Wf2o, wl + Wf2o,
                                  bufA, nullptr, nullptr, bf2, nullptr, NV, 128);

    // softmax -> d_out
    softmax128<<<smb, 256>>>(bufA, (float*)d_out, NV);
}